// round 1
// baseline (speedup 1.0000x reference)
#include <cuda_runtime.h>
#include <cuda_bf16.h>
#include <cstdint>
#include <cstddef>

// Problem constants (fixed shapes).
#define BATCH 4
#define SEQ   2048
#define DIM   1024   // D = DK = DV = 1024

// GEMM tiling
#define BM 128
#define BN 128
#define BK 8
#define TM 8
#define TN 8
#define NTHREADS 256

// ---------------------------------------------------------------------------
// Device scratch (allocation-free: __device__ globals)
// ---------------------------------------------------------------------------
__device__ float g_Q [(size_t)BATCH * SEQ * DIM];   // 33.5 MB
__device__ float g_K [(size_t)BATCH * SEQ * DIM];   // 33.5 MB
__device__ float g_V [(size_t)BATCH * SEQ * DIM];   // 33.5 MB
__device__ float g_S [(size_t)BATCH * SEQ * SEQ];   // 67 MB  (scores -> probs)
__device__ float g_AO[(size_t)BATCH * SEQ * DIM];   // 33.5 MB (attn @ V)

// ---------------------------------------------------------------------------
// SGEMM NN: C[M,N] = A[M,K] @ B[K,N], row-major, batched via blockIdx.z.
// causalKLimit: if nonzero, k-loop limited to (blockRow+1)*BM (P has zeros
// above the diagonal, so skipping them is exact).
// All dims are multiples of the tile sizes -> no bounds checks.
// ---------------------------------------------------------------------------
__global__ __launch_bounds__(NTHREADS)
void sgemm_nn(const float* __restrict__ Aall, const float* __restrict__ Ball,
              float* __restrict__ Call, int M, int N, int K,
              size_t strideA, size_t strideB, size_t strideC,
              int causalKLimit)
{
    const float* A = Aall + (size_t)blockIdx.z * strideA;
    const float* B = Ball + (size_t)blockIdx.z * strideB;
    float*       C = Call + (size_t)blockIdx.z * strideC;

    __shared__ float As[BK][BM];
    __shared__ float Bs[BK][BN];

    const int tid = threadIdx.x;
    const int threadCol = tid % (BN / TN);   // 0..15
    const int threadRow = tid / (BN / TN);   // 0..15

    const int innerRowA = tid / (BK / 4);          // 0..127
    const int innerColA = (tid % (BK / 4)) * 4;    // 0 or 4
    const int innerRowB = tid / (BN / 4);          // 0..7
    const int innerColB = (tid % (BN / 4)) * 4;    // 0..124

    const int row0 = blockIdx.y * BM;
    const int col0 = blockIdx.x * BN;

    int kEnd = K;
    if (causalKLimit) {
        int lim = (blockIdx.y + 1) * BM;
        if (lim < kEnd) kEnd = lim;
    }

    float acc[TM][TN] = {};
    float regM[TM], regN[TN];

    for (int k0 = 0; k0 < kEnd; k0 += BK) {
        float4 a4 = *reinterpret_cast<const float4*>(
            &A[(size_t)(row0 + innerRowA) * K + k0 + innerColA]);
        As[innerColA + 0][innerRowA] = a4.x;
        As[innerColA + 1][innerRowA] = a4.y;
        As[innerColA + 2][innerRowA] = a4.z;
        As[innerColA + 3][innerRowA] = a4.w;

        float4 b4 = *reinterpret_cast<const float4*>(
            &B[(size_t)(k0 + innerRowB) * N + col0 + innerColB]);
        *reinterpret_cast<float4*>(&Bs[innerRowB][innerColB]) = b4;

        __syncthreads();

        #pragma unroll
        for (int k = 0; k < BK; k++) {
            #pragma unroll
            for (int i = 0; i < TM; i++) regM[i] = As[k][threadRow * TM + i];
            #pragma unroll
            for (int j = 0; j < TN; j++) regN[j] = Bs[k][threadCol * TN + j];
            #pragma unroll
            for (int i = 0; i < TM; i++)
                #pragma unroll
                for (int j = 0; j < TN; j++)
                    acc[i][j] += regM[i] * regN[j];
        }
        __syncthreads();
    }

    #pragma unroll
    for (int i = 0; i < TM; i++) {
        const size_t r = (size_t)(row0 + threadRow * TM + i);
        #pragma unroll
        for (int j = 0; j < TN; j += 4) {
            float4 v = make_float4(acc[i][j], acc[i][j + 1],
                                   acc[i][j + 2], acc[i][j + 3]);
            *reinterpret_cast<float4*>(&C[r * N + col0 + threadCol * TN + j]) = v;
        }
    }
}

// ---------------------------------------------------------------------------
// SGEMM NT (scores): C[M,N] = A[M,K] @ B[N,K]^T  (both row-major), batched.
// Skips output tiles that are entirely above the causal diagonal.
// ---------------------------------------------------------------------------
__global__ __launch_bounds__(NTHREADS)
void sgemm_nt_causal(const float* __restrict__ Aall, const float* __restrict__ Ball,
                     float* __restrict__ Call, int M, int N, int K,
                     size_t strideA, size_t strideB, size_t strideC)
{
    const int row0 = blockIdx.y * BM;
    const int col0 = blockIdx.x * BN;
    if (col0 > row0 + BM - 1) return;   // fully masked tile

    const float* A = Aall + (size_t)blockIdx.z * strideA;
    const float* B = Ball + (size_t)blockIdx.z * strideB;
    float*       C = Call + (size_t)blockIdx.z * strideC;

    __shared__ float As[BK][BM];
    __shared__ float Bs[BK][BN];

    const int tid = threadIdx.x;
    const int threadCol = tid % (BN / TN);
    const int threadRow = tid / (BN / TN);

    const int innerRowA = tid / (BK / 4);
    const int innerColA = (tid % (BK / 4)) * 4;
    const int innerRowB = tid / (BK / 4);          // row within B tile (n dim)
    const int innerColB = (tid % (BK / 4)) * 4;    // k offset

    float acc[TM][TN] = {};
    float regM[TM], regN[TN];

    for (int k0 = 0; k0 < K; k0 += BK) {
        float4 a4 = *reinterpret_cast<const float4*>(
            &A[(size_t)(row0 + innerRowA) * K + k0 + innerColA]);
        As[innerColA + 0][innerRowA] = a4.x;
        As[innerColA + 1][innerRowA] = a4.y;
        As[innerColA + 2][innerRowA] = a4.z;
        As[innerColA + 3][innerRowA] = a4.w;

        float4 b4 = *reinterpret_cast<const float4*>(
            &B[(size_t)(col0 + innerRowB) * K + k0 + innerColB]);
        Bs[innerColB + 0][innerRowB] = b4.x;
        Bs[innerColB + 1][innerRowB] = b4.y;
        Bs[innerColB + 2][innerRowB] = b4.z;
        Bs[innerColB + 3][innerRowB] = b4.w;

        __syncthreads();

        #pragma unroll
        for (int k = 0; k < BK; k++) {
            #pragma unroll
            for (int i = 0; i < TM; i++) regM[i] = As[k][threadRow * TM + i];
            #pragma unroll
            for (int j = 0; j < TN; j++) regN[j] = Bs[k][threadCol * TN + j];
            #pragma unroll
            for (int i = 0; i < TM; i++)
                #pragma unroll
                for (int j = 0; j < TN; j++)
                    acc[i][j] += regM[i] * regN[j];
        }
        __syncthreads();
    }

    #pragma unroll
    for (int i = 0; i < TM; i++) {
        const size_t r = (size_t)(row0 + threadRow * TM + i);
        #pragma unroll
        for (int j = 0; j < TN; j += 4) {
            float4 v = make_float4(acc[i][j], acc[i][j + 1],
                                   acc[i][j + 2], acc[i][j + 3]);
            *reinterpret_cast<float4*>(&C[r * N + col0 + threadCol * TN + j]) = v;
        }
    }
}

// ---------------------------------------------------------------------------
// Causal softmax over rows of S (in place), writing zeros above the diagonal
// so the PV GEMM can run as a plain (k-limited) GEMM.
// Reference semantics: masked entries -> -FLT_MAX, then *scale, then softmax
// == softmax over j<=i of (s_ij * scale).
// ---------------------------------------------------------------------------
__global__ void softmax_causal(float* __restrict__ Sbuf)
{
    const int i = blockIdx.x;      // query position
    const int b = blockIdx.y;      // batch
    float* row = Sbuf + ((size_t)b * SEQ + i) * SEQ;
    const int n = i + 1;           // valid length
    const float scale = 0.03125f;  // 1/sqrt(1024)

    __shared__ float red[256];
    const int tid = threadIdx.x;

    float m = -3.402823466e+38f;
    for (int j = tid; j < n; j += 256) m = fmaxf(m, row[j]);
    red[tid] = m;
    __syncthreads();
    #pragma unroll
    for (int s = 128; s > 0; s >>= 1) {
        if (tid < s) red[tid] = fmaxf(red[tid], red[tid + s]);
        __syncthreads();
    }
    const float mx = red[0] * scale;   // scale>0 -> max(s*scale) = scale*max(s)
    __syncthreads();

    float sum = 0.0f;
    for (int j = tid; j < n; j += 256) sum += __expf(row[j] * scale - mx);
    red[tid] = sum;
    __syncthreads();
    #pragma unroll
    for (int s = 128; s > 0; s >>= 1) {
        if (tid < s) red[tid] += red[tid + s];
        __syncthreads();
    }
    const float inv = 1.0f / red[0];

    for (int j = tid; j < n; j += 256)
        row[j] = __expf(row[j] * scale - mx) * inv;
    for (int j = n + tid; j < SEQ; j += 256)
        row[j] = 0.0f;
}

// ---------------------------------------------------------------------------
// Launch
// ---------------------------------------------------------------------------
extern "C" void kernel_launch(void* const* d_in, const int* in_sizes, int n_in,
                              void* d_out, int out_size)
{
    const float* x  = (const float*)d_in[0];   // [B,S,D]
    const float* Wq = (const float*)d_in[1];   // [D,DK]
    const float* Wk = (const float*)d_in[2];   // [D,DK]
    const float* Wv = (const float*)d_in[3];   // [D,DV]
    const float* Wo = (const float*)d_in[4];   // [DV,DV]
    float* out = (float*)d_out;                // [B,S,DV]

    float *Q, *K, *V, *S, *AO;
    cudaGetSymbolAddress((void**)&Q,  g_Q);
    cudaGetSymbolAddress((void**)&K,  g_K);
    cudaGetSymbolAddress((void**)&V,  g_V);
    cudaGetSymbolAddress((void**)&S,  g_S);
    cudaGetSymbolAddress((void**)&AO, g_AO);

    const int MX = BATCH * SEQ;          // 8192 flattened rows
    const size_t sQKV = (size_t)SEQ * DIM;
    const size_t sS   = (size_t)SEQ * SEQ;

    dim3 blk(NTHREADS);

    // Q/K/V projections: [8192,1024] @ [1024,1024]
    dim3 gProj(DIM / BN, MX / BM, 1);
    sgemm_nn<<<gProj, blk>>>(x, Wq, Q, MX, DIM, DIM, 0, 0, 0, 0);
    sgemm_nn<<<gProj, blk>>>(x, Wk, K, MX, DIM, DIM, 0, 0, 0, 0);
    sgemm_nn<<<gProj, blk>>>(x, Wv, V, MX, DIM, DIM, 0, 0, 0, 0);

    // scores = Q @ K^T per batch (lower-triangular tiles only)
    dim3 gScores(SEQ / BN, SEQ / BM, BATCH);
    sgemm_nt_causal<<<gScores, blk>>>(Q, K, S, SEQ, SEQ, DIM, sQKV, sQKV, sS);

    // causal softmax in place
    softmax_causal<<<dim3(SEQ, BATCH), 256>>>(S);

    // AO = P @ V per batch (k-loop limited by causality)
    dim3 gPV(DIM / BN, SEQ / BM, BATCH);
    sgemm_nn<<<gPV, blk>>>(S, V, AO, SEQ, DIM, SEQ, sS, sQKV, sQKV, 1);

    // out = AO @ Wo
    dim3 gOut(DIM / BN, MX / BM, 1);
    sgemm_nn<<<gOut, blk>>>(AO, Wo, out, MX, DIM, DIM, 0, 0, 0, 0);
}

// round 2
// speedup vs baseline: 1.0171x; 1.0171x over previous
#include <cuda_runtime.h>
#include <cuda_bf16.h>
#include <cstdint>
#include <cstddef>

// Problem constants (fixed shapes).
#define BATCH 4
#define SEQ   2048
#define DIM   1024   // D = DK = DV = 1024

// GEMM tiling
#define BM 128
#define BN 128
#define BK 8
#define TM 8
#define TN 8
#define NTHREADS 256

// ---------------------------------------------------------------------------
// Packed fp32x2 FMA helpers (Blackwell sm_103a). ptxas never auto-fuses two
// FFMA into FFMA2; only PTX fma.rn.f32x2 reaches it. Each op = 2 fp32 FMAs
// in one FMA-pipe issue slot.
// ---------------------------------------------------------------------------
__device__ __forceinline__ void fma2(unsigned long long& d,
                                     unsigned long long a,
                                     unsigned long long b) {
    asm("fma.rn.f32x2 %0, %1, %2, %0;" : "+l"(d) : "l"(a), "l"(b));
}
__device__ __forceinline__ unsigned long long bcast2(float x) {
    unsigned long long r;
    asm("mov.b64 %0, {%1, %1};" : "=l"(r) : "f"(x));
    return r;
}
__device__ __forceinline__ float2 unpack2(unsigned long long v) {
    float lo, hi;
    asm("mov.b64 {%0, %1}, %2;" : "=f"(lo), "=f"(hi) : "l"(v));
    return make_float2(lo, hi);
}

// ---------------------------------------------------------------------------
// Device scratch (allocation-free: __device__ globals)
// ---------------------------------------------------------------------------
__device__ float g_Q [(size_t)BATCH * SEQ * DIM];
__device__ float g_K [(size_t)BATCH * SEQ * DIM];
__device__ float g_V [(size_t)BATCH * SEQ * DIM];
__device__ float g_S [(size_t)BATCH * SEQ * SEQ];
__device__ float g_AO[(size_t)BATCH * SEQ * DIM];

// ---------------------------------------------------------------------------
// Shared microkernel: 8x8 per-thread outer product using f32x2 pairs along N.
// acc2[i][j4] holds (C[i][2*j4], C[i][2*j4+1]).
// ---------------------------------------------------------------------------
struct Frag { unsigned long long acc2[TM][TN / 2]; };

__device__ __forceinline__ void micro_step(const float (*As)[BM],
                                           const float (*Bs)[BN],
                                           int threadRow, int threadCol,
                                           Frag& f) {
    #pragma unroll
    for (int k = 0; k < BK; k++) {
        unsigned long long regN[TN / 2];
        #pragma unroll
        for (int j = 0; j < TN / 2; j++)
            regN[j] = *reinterpret_cast<const unsigned long long*>(
                &Bs[k][threadCol * TN + 2 * j]);
        #pragma unroll
        for (int i = 0; i < TM; i++) {
            unsigned long long mm = bcast2(As[k][threadRow * TM + i]);
            #pragma unroll
            for (int j = 0; j < TN / 2; j++)
                fma2(f.acc2[i][j], mm, regN[j]);
        }
    }
}

__device__ __forceinline__ void store_frag(float* __restrict__ C, int N,
                                           int row0, int col0,
                                           int threadRow, int threadCol,
                                           const Frag& f) {
    #pragma unroll
    for (int i = 0; i < TM; i++) {
        const size_t r = (size_t)(row0 + threadRow * TM + i);
        #pragma unroll
        for (int j = 0; j < TN / 2; j += 2) {
            float2 p0 = unpack2(f.acc2[i][j]);
            float2 p1 = unpack2(f.acc2[i][j + 1]);
            float4 v = make_float4(p0.x, p0.y, p1.x, p1.y);
            *reinterpret_cast<float4*>(
                &C[r * N + col0 + threadCol * TN + 2 * j]) = v;
        }
    }
}

// ---------------------------------------------------------------------------
// SGEMM NN: C[M,N] = A[M,K] @ B[K,N], row-major, batched via blockIdx.z.
// causalKLimit: if nonzero, k-loop limited to (blockRow+1)*BM.
// ---------------------------------------------------------------------------
__global__ __launch_bounds__(NTHREADS)
void sgemm_nn(const float* __restrict__ Aall, const float* __restrict__ Ball,
              float* __restrict__ Call, int M, int N, int K,
              size_t strideA, size_t strideB, size_t strideC,
              int causalKLimit)
{
    const float* A = Aall + (size_t)blockIdx.z * strideA;
    const float* B = Ball + (size_t)blockIdx.z * strideB;
    float*       C = Call + (size_t)blockIdx.z * strideC;

    __shared__ float As[BK][BM];
    __shared__ float Bs[BK][BN];

    const int tid = threadIdx.x;
    const int threadCol = tid % (BN / TN);
    const int threadRow = tid / (BN / TN);

    const int innerRowA = tid / (BK / 4);
    const int innerColA = (tid % (BK / 4)) * 4;
    const int innerRowB = tid / (BN / 4);
    const int innerColB = (tid % (BN / 4)) * 4;

    const int row0 = blockIdx.y * BM;
    const int col0 = blockIdx.x * BN;

    int kEnd = K;
    if (causalKLimit) {
        int lim = (blockIdx.y + 1) * BM;
        if (lim < kEnd) kEnd = lim;
    }

    Frag f = {};

    for (int k0 = 0; k0 < kEnd; k0 += BK) {
        float4 a4 = *reinterpret_cast<const float4*>(
            &A[(size_t)(row0 + innerRowA) * K + k0 + innerColA]);
        As[innerColA + 0][innerRowA] = a4.x;
        As[innerColA + 1][innerRowA] = a4.y;
        As[innerColA + 2][innerRowA] = a4.z;
        As[innerColA + 3][innerRowA] = a4.w;

        float4 b4 = *reinterpret_cast<const float4*>(
            &B[(size_t)(k0 + innerRowB) * N + col0 + innerColB]);
        *reinterpret_cast<float4*>(&Bs[innerRowB][innerColB]) = b4;

        __syncthreads();
        micro_step(As, Bs, threadRow, threadCol, f);
        __syncthreads();
    }

    store_frag(C, N, row0, col0, threadRow, threadCol, f);
}

// ---------------------------------------------------------------------------
// SGEMM NT (scores): C[M,N] = A[M,K] @ B[N,K]^T, batched; skips tiles fully
// above the causal diagonal.
// ---------------------------------------------------------------------------
__global__ __launch_bounds__(NTHREADS)
void sgemm_nt_causal(const float* __restrict__ Aall, const float* __restrict__ Ball,
                     float* __restrict__ Call, int M, int N, int K,
                     size_t strideA, size_t strideB, size_t strideC)
{
    const int row0 = blockIdx.y * BM;
    const int col0 = blockIdx.x * BN;
    if (col0 > row0 + BM - 1) return;   // fully masked tile

    const float* A = Aall + (size_t)blockIdx.z * strideA;
    const float* B = Ball + (size_t)blockIdx.z * strideB;
    float*       C = Call + (size_t)blockIdx.z * strideC;

    __shared__ float As[BK][BM];
    __shared__ float Bs[BK][BN];

    const int tid = threadIdx.x;
    const int threadCol = tid % (BN / TN);
    const int threadRow = tid / (BN / TN);

    const int innerRowA = tid / (BK / 4);
    const int innerColA = (tid % (BK / 4)) * 4;
    const int innerRowB = tid / (BK / 4);
    const int innerColB = (tid % (BK / 4)) * 4;

    Frag f = {};

    for (int k0 = 0; k0 < K; k0 += BK) {
        float4 a4 = *reinterpret_cast<const float4*>(
            &A[(size_t)(row0 + innerRowA) * K + k0 + innerColA]);
        As[innerColA + 0][innerRowA] = a4.x;
        As[innerColA + 1][innerRowA] = a4.y;
        As[innerColA + 2][innerRowA] = a4.z;
        As[innerColA + 3][innerRowA] = a4.w;

        float4 b4 = *reinterpret_cast<const float4*>(
            &B[(size_t)(col0 + innerRowB) * K + k0 + innerColB]);
        Bs[innerColB + 0][innerRowB] = b4.x;
        Bs[innerColB + 1][innerRowB] = b4.y;
        Bs[innerColB + 2][innerRowB] = b4.z;
        Bs[innerColB + 3][innerRowB] = b4.w;

        __syncthreads();
        micro_step(As, Bs, threadRow, threadCol, f);
        __syncthreads();
    }

    store_frag(C, N, row0, col0, threadRow, threadCol, f);
}

// ---------------------------------------------------------------------------
// Causal softmax over rows of S (in place); zeros above the diagonal so PV
// runs as a k-limited plain GEMM.
// ---------------------------------------------------------------------------
__global__ void softmax_causal(float* __restrict__ Sbuf)
{
    const int i = blockIdx.x;
    const int b = blockIdx.y;
    float* row = Sbuf + ((size_t)b * SEQ + i) * SEQ;
    const int n = i + 1;
    const float scale = 0.03125f;  // 1/sqrt(1024)

    __shared__ float red[256];
    const int tid = threadIdx.x;

    float m = -3.402823466e+38f;
    for (int j = tid; j < n; j += 256) m = fmaxf(m, row[j]);
    red[tid] = m;
    __syncthreads();
    #pragma unroll
    for (int s = 128; s > 0; s >>= 1) {
        if (tid < s) red[tid] = fmaxf(red[tid], red[tid + s]);
        __syncthreads();
    }
    const float mx = red[0] * scale;
    __syncthreads();

    float sum = 0.0f;
    for (int j = tid; j < n; j += 256) sum += __expf(row[j] * scale - mx);
    red[tid] = sum;
    __syncthreads();
    #pragma unroll
    for (int s = 128; s > 0; s >>= 1) {
        if (tid < s) red[tid] += red[tid + s];
        __syncthreads();
    }
    const float inv = 1.0f / red[0];

    for (int j = tid; j < n; j += 256)
        row[j] = __expf(row[j] * scale - mx) * inv;
    for (int j = n + tid; j < SEQ; j += 256)
        row[j] = 0.0f;
}

// ---------------------------------------------------------------------------
// Launch
// ---------------------------------------------------------------------------
extern "C" void kernel_launch(void* const* d_in, const int* in_sizes, int n_in,
                              void* d_out, int out_size)
{
    const float* x  = (const float*)d_in[0];   // [B,S,D]
    const float* Wq = (const float*)d_in[1];   // [D,DK]
    const float* Wk = (const float*)d_in[2];   // [D,DK]
    const float* Wv = (const float*)d_in[3];   // [D,DV]
    const float* Wo = (const float*)d_in[4];   // [DV,DV]
    float* out = (float*)d_out;                // [B,S,DV]

    float *Q, *K, *V, *S, *AO;
    cudaGetSymbolAddress((void**)&Q,  g_Q);
    cudaGetSymbolAddress((void**)&K,  g_K);
    cudaGetSymbolAddress((void**)&V,  g_V);
    cudaGetSymbolAddress((void**)&S,  g_S);
    cudaGetSymbolAddress((void**)&AO, g_AO);

    const int MX = BATCH * SEQ;          // 8192 flattened rows
    const size_t sQKV = (size_t)SEQ * DIM;
    const size_t sS   = (size_t)SEQ * SEQ;

    dim3 blk(NTHREADS);

    // Q/K/V projections: [8192,1024] @ [1024,1024]
    dim3 gProj(DIM / BN, MX / BM, 1);
    sgemm_nn<<<gProj, blk>>>(x, Wq, Q, MX, DIM, DIM, 0, 0, 0, 0);
    sgemm_nn<<<gProj, blk>>>(x, Wk, K, MX, DIM, DIM, 0, 0, 0, 0);
    sgemm_nn<<<gProj, blk>>>(x, Wv, V, MX, DIM, DIM, 0, 0, 0, 0);

    // scores = Q @ K^T per batch (lower-triangular tiles only)
    dim3 gScores(SEQ / BN, SEQ / BM, BATCH);
    sgemm_nt_causal<<<gScores, blk>>>(Q, K, S, SEQ, SEQ, DIM, sQKV, sQKV, sS);

    // causal softmax in place
    softmax_causal<<<dim3(SEQ, BATCH), 256>>>(S);

    // AO = P @ V per batch (k-loop limited by causality)
    dim3 gPV(DIM / BN, SEQ / BM, BATCH);
    sgemm_nn<<<gPV, blk>>>(S, V, AO, SEQ, DIM, SEQ, sS, sQKV, sQKV, 1);

    // out = AO @ Wo
    dim3 gOut(DIM / BN, MX / BM, 1);
    sgemm_nn<<<gOut, blk>>>(AO, Wo, out, MX, DIM, DIM, 0, 0, 0, 0);
}

// round 4
// speedup vs baseline: 2.7262x; 2.6804x over previous
#include <cuda_runtime.h>
#include <cuda_bf16.h>
#include <cstdint>
#include <cstddef>

// ---------------------------------------------------------------------------
// Problem constants
// ---------------------------------------------------------------------------
#define BATCH 4
#define SEQ   2048
#define DIM   1024

// HMMA GEMM tiling: 128x128 CTA tile, 8 warps of 64x32, K chunks of 64 bf16.
#define KC     64
#define LDT    72                         // padded row stride in bf16 (144 B)
#define TILE_P (128 * LDT * 2)            // 18432 B per tile
#define STG_B  (4 * TILE_P)               // Ahi, Alo, Bhi, Blo = 73728 B
#define SMEM_B (2 * STG_B)                // double buffered = 147456 B
#define TCN    256

// ---------------------------------------------------------------------------
// PTX helpers (base sm_103 ISA only: cp.async, ldmatrix, mma.sync)
// ---------------------------------------------------------------------------
__device__ __forceinline__ uint32_t smem_u32(const void* p) {
    uint32_t a;
    asm("{ .reg .u64 t; cvta.to.shared.u64 t, %1; cvt.u32.u64 %0, t; }"
        : "=r"(a) : "l"(p));
    return a;
}
__device__ __forceinline__ void cpa16(uint32_t dst, const void* src) {
    asm volatile("cp.async.cg.shared.global [%0], [%1], 16;"
                 :: "r"(dst), "l"(src));
}
__device__ __forceinline__ void cpa_commit() {
    asm volatile("cp.async.commit_group;");
}
__device__ __forceinline__ void ldm_x4(uint32_t* r, uint32_t addr) {
    asm volatile("ldmatrix.sync.aligned.m8n8.x4.shared.b16 {%0,%1,%2,%3}, [%4];"
                 : "=r"(r[0]), "=r"(r[1]), "=r"(r[2]), "=r"(r[3]) : "r"(addr));
}
__device__ __forceinline__ void mma16816(float* d, const uint32_t* a,
                                         uint32_t b0, uint32_t b1) {
    asm volatile(
        "mma.sync.aligned.m16n8k16.row.col.f32.bf16.bf16.f32 "
        "{%0,%1,%2,%3}, {%4,%5,%6,%7}, {%8,%9}, {%0,%1,%2,%3};"
        : "+f"(d[0]), "+f"(d[1]), "+f"(d[2]), "+f"(d[3])
        : "r"(a[0]), "r"(a[1]), "r"(a[2]), "r"(a[3]), "r"(b0), "r"(b1));
}

// bf16 split helpers
__device__ __forceinline__ void split_pack2(float a, float b,
                                            uint32_t& hp, uint32_t& lp) {
    __nv_bfloat16 ha = __float2bfloat16_rn(a), hb = __float2bfloat16_rn(b);
    float la = a - __bfloat162float(ha);
    float lb = b - __bfloat162float(hb);
    __nv_bfloat16 lA = __float2bfloat16_rn(la), lB = __float2bfloat16_rn(lb);
    hp = (uint32_t)__bfloat16_as_ushort(ha) |
         ((uint32_t)__bfloat16_as_ushort(hb) << 16);
    lp = (uint32_t)__bfloat16_as_ushort(lA) |
         ((uint32_t)__bfloat16_as_ushort(lB) << 16);
}

// ---------------------------------------------------------------------------
// Device scratch
// ---------------------------------------------------------------------------
#define RXD ((size_t)BATCH * SEQ * DIM)
#define RSS ((size_t)BATCH * SEQ * SEQ)
__device__ __nv_bfloat16 g_xhi[RXD],  g_xlo[RXD];
__device__ __nv_bfloat16 g_wqth[DIM * DIM], g_wqtl[DIM * DIM];
__device__ __nv_bfloat16 g_wkth[DIM * DIM], g_wktl[DIM * DIM];
__device__ __nv_bfloat16 g_wvth[DIM * DIM], g_wvtl[DIM * DIM];
__device__ __nv_bfloat16 g_woth[DIM * DIM], g_wotl[DIM * DIM];
__device__ __nv_bfloat16 g_qhi[RXD], g_qlo[RXD], g_khi[RXD], g_klo[RXD];
__device__ __nv_bfloat16 g_vthi[RXD], g_vtlo[RXD];   // [B][DV][SEQ]
__device__ float         g_S[RSS];
__device__ __nv_bfloat16 g_phi[RSS], g_plo[RSS];
__device__ __nv_bfloat16 g_aohi[RXD], g_aolo[RXD];

// ---------------------------------------------------------------------------
// Async tile load: 128 rows x 64 bf16 (K-major) -> padded smem (stride LDT)
// ---------------------------------------------------------------------------
__device__ __forceinline__ void load_tile_async(uint32_t base,
                                                const __nv_bfloat16* __restrict__ gp,
                                                int ld, int tid) {
    #pragma unroll
    for (int i = 0; i < 4; i++) {
        int idx = i * TCN + tid;          // 0..1023
        int row = idx >> 3;
        int c16 = idx & 7;
        cpa16(base + row * (LDT * 2) + c16 * 16,
              gp + (size_t)row * ld + c16 * 8);
    }
}

// ---------------------------------------------------------------------------
// HMMA split-bf16 GEMM: C[M,N] = A[M,K] @ B[N,K]^T (both row-major, K-major)
// MODE: 0 = fp32 out, 1 = split bf16 out, 2 = split bf16 transposed out (V^T)
// CAUSAL: 0 none, 1 = skip tiles above diagonal (scores), 2 = K-limit (PV)
// ---------------------------------------------------------------------------
template<int MODE, int CAUSAL>
__global__ __launch_bounds__(TCN)
void hm_gemm(const __nv_bfloat16* __restrict__ Ahi, const __nv_bfloat16* __restrict__ Alo,
             const __nv_bfloat16* __restrict__ Bhi, const __nv_bfloat16* __restrict__ Blo,
             float* __restrict__ C32,
             __nv_bfloat16* __restrict__ Chi, __nv_bfloat16* __restrict__ Clo,
             int Nld, int Kdim, size_t sA, size_t sB, size_t sC)
{
    if (CAUSAL == 1 && blockIdx.x > blockIdx.y) return;

    const int row0 = blockIdx.y * 128;
    const int col0 = blockIdx.x * 128;
    const size_t zb = blockIdx.z;

    extern __shared__ char smem[];
    const uint32_t sb = smem_u32(smem);
    const int tid  = threadIdx.x;
    const int wid  = tid >> 5;
    const int lane = tid & 31;
    const int warp_m = wid >> 2;          // 0..1
    const int warp_n = wid & 3;           // 0..3
    const int gq = lane >> 2;             // groupID 0..7
    const int tq = lane & 3;              // 0..3

    int kEnd = Kdim;
    if (CAUSAL == 2) {
        int lim = (blockIdx.y + 1) * 128;
        if (lim < kEnd) kEnd = lim;
    }
    const int nChunks = kEnd / KC;

    const __nv_bfloat16* pAh = Ahi + zb * sA + (size_t)row0 * Kdim;
    const __nv_bfloat16* pAl = Alo + zb * sA + (size_t)row0 * Kdim;
    const __nv_bfloat16* pBh = Bhi + zb * sB + (size_t)col0 * Kdim;
    const __nv_bfloat16* pBl = Blo + zb * sB + (size_t)col0 * Kdim;

    // ldmatrix lane address offsets (within a tile, bytes)
    // A x4: lanes 0-7 rows r k0 | 8-15 rows r+8 k0 | 16-23 rows r k8 | 24-31 rows r+8 k8
    const int a_r  = lane & 15;
    const int a_kq = (lane >> 4) << 3;
    // B x4: lanes 0-7 n r k0 | 8-15 n r k8 | 16-23 n r+8 k0 | 24-31 n r+8 k8
    const int b_r  = (lane & 7) + ((lane >= 16) ? 8 : 0);
    const int b_kq = ((lane >> 3) & 1) << 3;

    float acc[4][4][4];
    #pragma unroll
    for (int i = 0; i < 4; i++)
        #pragma unroll
        for (int j = 0; j < 4; j++)
            #pragma unroll
            for (int q = 0; q < 4; q++) acc[i][j][q] = 0.0f;

    // prefetch chunk 0
    {
        const uint32_t st = sb;
        load_tile_async(st,              pAh, Kdim, tid);
        load_tile_async(st + TILE_P,     pAl, Kdim, tid);
        load_tile_async(st + 2 * TILE_P, pBh, Kdim, tid);
        load_tile_async(st + 3 * TILE_P, pBl, Kdim, tid);
        cpa_commit();
    }

    for (int c = 0; c < nChunks; c++) {
        if (c + 1 < nChunks) {
            const uint32_t st = sb + ((c + 1) & 1) * STG_B;
            const int k0 = (c + 1) * KC;
            load_tile_async(st,              pAh + k0, Kdim, tid);
            load_tile_async(st + TILE_P,     pAl + k0, Kdim, tid);
            load_tile_async(st + 2 * TILE_P, pBh + k0, Kdim, tid);
            load_tile_async(st + 3 * TILE_P, pBl + k0, Kdim, tid);
            cpa_commit();
            asm volatile("cp.async.wait_group 1;");
        } else {
            asm volatile("cp.async.wait_group 0;");
        }
        __syncthreads();

        const uint32_t st = sb + (c & 1) * STG_B;
        #pragma unroll
        for (int ks = 0; ks < 4; ks++) {
            const int k0 = ks * 16;
            uint32_t ah[4][4], al[4][4], bh[2][4], bl[2][4];
            #pragma unroll
            for (int mb = 0; mb < 4; mb++) {
                const uint32_t aoff =
                    (warp_m * 64 + mb * 16 + a_r) * (LDT * 2) + (k0 + a_kq) * 2;
                ldm_x4(ah[mb], st + aoff);
                ldm_x4(al[mb], st + TILE_P + aoff);
            }
            #pragma unroll
            for (int nh = 0; nh < 2; nh++) {
                const uint32_t boff =
                    (warp_n * 32 + nh * 16 + b_r) * (LDT * 2) + (k0 + b_kq) * 2;
                ldm_x4(bh[nh], st + 2 * TILE_P + boff);
                ldm_x4(bl[nh], st + 3 * TILE_P + boff);
            }
            #pragma unroll
            for (int mb = 0; mb < 4; mb++) {
                #pragma unroll
                for (int nb = 0; nb < 4; nb++) {
                    const int nh = nb >> 1, p = (nb & 1) * 2;
                    mma16816(acc[mb][nb], ah[mb], bh[nh][p], bh[nh][p + 1]);
                    mma16816(acc[mb][nb], ah[mb], bl[nh][p], bl[nh][p + 1]);
                    mma16816(acc[mb][nb], al[mb], bh[nh][p], bh[nh][p + 1]);
                }
            }
        }
        __syncthreads();
    }

    // ---------------- Epilogue ----------------
    if (MODE != 2) {
        #pragma unroll
        for (int mb = 0; mb < 4; mb++) {
            const int m = row0 + warp_m * 64 + mb * 16 + gq;
            #pragma unroll
            for (int nb = 0; nb < 4; nb++) {
                const int n = col0 + warp_n * 32 + nb * 8 + tq * 2;
                const float* cc = acc[mb][nb];
                if (MODE == 0) {
                    float* d0 = C32 + zb * sC + (size_t)m * Nld + n;
                    float* d1 = C32 + zb * sC + (size_t)(m + 8) * Nld + n;
                    *reinterpret_cast<float2*>(d0) = make_float2(cc[0], cc[1]);
                    *reinterpret_cast<float2*>(d1) = make_float2(cc[2], cc[3]);
                } else {
                    uint32_t hp, lp;
                    size_t o0 = zb * sC + (size_t)m * Nld + n;
                    size_t o1 = zb * sC + (size_t)(m + 8) * Nld + n;
                    split_pack2(cc[0], cc[1], hp, lp);
                    *reinterpret_cast<uint32_t*>(Chi + o0) = hp;
                    *reinterpret_cast<uint32_t*>(Clo + o0) = lp;
                    split_pack2(cc[2], cc[3], hp, lp);
                    *reinterpret_cast<uint32_t*>(Chi + o1) = hp;
                    *reinterpret_cast<uint32_t*>(Clo + o1) = lp;
                }
            }
        }
    } else {
        // transposed split output: tile rows = s, cols = dv; write [dv][s]
        float* smt = reinterpret_cast<float*>(smem);   // [128][129]
        __syncthreads();
        #pragma unroll
        for (int mb = 0; mb < 4; mb++) {
            const int m = warp_m * 64 + mb * 16 + gq;
            #pragma unroll
            for (int nb = 0; nb < 4; nb++) {
                const int n = warp_n * 32 + nb * 8 + tq * 2;
                const float* cc = acc[mb][nb];
                smt[m * 129 + n]           = cc[0];
                smt[m * 129 + n + 1]       = cc[1];
                smt[(m + 8) * 129 + n]     = cc[2];
                smt[(m + 8) * 129 + n + 1] = cc[3];
            }
        }
        __syncthreads();
        const int b  = row0 >> 11;
        const int s0 = row0 & (SEQ - 1);
        const int n  = tid >> 1;            // 0..127 (dv within tile)
        const int sh = (tid & 1) * 64;      // s half
        const size_t base = (size_t)b * DIM * SEQ +
                            (size_t)(col0 + n) * SEQ + s0 + sh;
        #pragma unroll
        for (int u = 0; u < 64; u += 2) {
            uint32_t hp, lp;
            split_pack2(smt[(sh + u) * 129 + n], smt[(sh + u + 1) * 129 + n],
                        hp, lp);
            *reinterpret_cast<uint32_t*>(Chi + base + u) = hp;
            *reinterpret_cast<uint32_t*>(Clo + base + u) = lp;
        }
    }
}

// ---------------------------------------------------------------------------
// Preprocess: fp32 -> bf16 hi/lo split (same layout)
// ---------------------------------------------------------------------------
__global__ void split_kernel(const float* __restrict__ in,
                             __nv_bfloat16* __restrict__ hi,
                             __nv_bfloat16* __restrict__ lo, size_t n4)
{
    size_t i = (size_t)blockIdx.x * blockDim.x + threadIdx.x;
    if (i >= n4) return;
    float4 v = reinterpret_cast<const float4*>(in)[i];
    uint32_t h0, l0, h1, l1;
    split_pack2(v.x, v.y, h0, l0);
    split_pack2(v.z, v.w, h1, l1);
    reinterpret_cast<uint2*>(hi)[i] = make_uint2(h0, h1);
    reinterpret_cast<uint2*>(lo)[i] = make_uint2(l0, l1);
}

// W [K][N] fp32 -> Wt hi/lo [N][K] bf16 (1024x1024)
__global__ void transpose_split(const float* __restrict__ in,
                                __nv_bfloat16* __restrict__ thi,
                                __nv_bfloat16* __restrict__ tlo)
{
    __shared__ float t[32][33];
    const int bx = blockIdx.x * 32, by = blockIdx.y * 32;
    const int x = threadIdx.x, y = threadIdx.y;   // 32 x 8
    #pragma unroll
    for (int i = 0; i < 32; i += 8)
        t[y + i][x] = in[(size_t)(by + y + i) * DIM + bx + x];
    __syncthreads();
    #pragma unroll
    for (int i = 0; i < 32; i += 8) {
        float v = t[x][y + i];
        __nv_bfloat16 h = __float2bfloat16_rn(v);
        float lv = v - __bfloat162float(h);
        size_t o = (size_t)(bx + y + i) * DIM + by + x;
        thi[o] = h;
        tlo[o] = __float2bfloat16_rn(lv);
    }
}

// ---------------------------------------------------------------------------
// Causal softmax: reads fp32 S, writes split-bf16 P (zeros above diagonal)
// ---------------------------------------------------------------------------
__global__ void softmax_causal(const float* __restrict__ Sbuf,
                               __nv_bfloat16* __restrict__ Phi,
                               __nv_bfloat16* __restrict__ Plo)
{
    const int i = blockIdx.x;
    const int b = blockIdx.y;
    const size_t off = ((size_t)b * SEQ + i) * SEQ;
    const float* row = Sbuf + off;
    const int n = i + 1;
    const float scale = 0.03125f;   // 1/sqrt(1024)

    __shared__ float red[256];
    const int tid = threadIdx.x;

    float m = -3.402823466e+38f;
    for (int j = tid; j < n; j += 256) m = fmaxf(m, row[j]);
    red[tid] = m;
    __syncthreads();
    #pragma unroll
    for (int s = 128; s > 0; s >>= 1) {
        if (tid < s) red[tid] = fmaxf(red[tid], red[tid + s]);
        __syncthreads();
    }
    const float mx = red[0] * scale;
    __syncthreads();

    float sum = 0.0f;
    for (int j = tid; j < n; j += 256) sum += __expf(row[j] * scale - mx);
    red[tid] = sum;
    __syncthreads();
    #pragma unroll
    for (int s = 128; s > 0; s >>= 1) {
        if (tid < s) red[tid] += red[tid + s];
        __syncthreads();
    }
    const float inv = 1.0f / red[0];

    for (int j = tid; j < n; j += 256) {
        float p = __expf(row[j] * scale - mx) * inv;
        __nv_bfloat16 h = __float2bfloat16_rn(p);
        Phi[off + j] = h;
        Plo[off + j] = __float2bfloat16_rn(p - __bfloat162float(h));
    }
    const __nv_bfloat16 z = __float2bfloat16_rn(0.0f);
    for (int j = n + tid; j < SEQ; j += 256) {
        Phi[off + j] = z;
        Plo[off + j] = z;
    }
}

// ---------------------------------------------------------------------------
// Launch
// ---------------------------------------------------------------------------
extern "C" void kernel_launch(void* const* d_in, const int* in_sizes, int n_in,
                              void* d_out, int out_size)
{
    const float* x  = (const float*)d_in[0];
    const float* Wq = (const float*)d_in[1];
    const float* Wk = (const float*)d_in[2];
    const float* Wv = (const float*)d_in[3];
    const float* Wo = (const float*)d_in[4];
    float* out = (float*)d_out;

    cudaFuncSetAttribute(hm_gemm<1,0>, cudaFuncAttributeMaxDynamicSharedMemorySize, SMEM_B);
    cudaFuncSetAttribute(hm_gemm<2,0>, cudaFuncAttributeMaxDynamicSharedMemorySize, SMEM_B);
    cudaFuncSetAttribute(hm_gemm<0,1>, cudaFuncAttributeMaxDynamicSharedMemorySize, SMEM_B);
    cudaFuncSetAttribute(hm_gemm<1,2>, cudaFuncAttributeMaxDynamicSharedMemorySize, SMEM_B);
    cudaFuncSetAttribute(hm_gemm<0,0>, cudaFuncAttributeMaxDynamicSharedMemorySize, SMEM_B);

    __nv_bfloat16 *xhi, *xlo, *wqth, *wqtl, *wkth, *wktl, *wvth, *wvtl, *woth, *wotl;
    __nv_bfloat16 *qhi, *qlo, *khi, *klo, *vthi, *vtlo, *phi, *plo, *aohi, *aolo;
    float* S;
    cudaGetSymbolAddress((void**)&xhi, g_xhi);   cudaGetSymbolAddress((void**)&xlo, g_xlo);
    cudaGetSymbolAddress((void**)&wqth, g_wqth); cudaGetSymbolAddress((void**)&wqtl, g_wqtl);
    cudaGetSymbolAddress((void**)&wkth, g_wkth); cudaGetSymbolAddress((void**)&wktl, g_wktl);
    cudaGetSymbolAddress((void**)&wvth, g_wvth); cudaGetSymbolAddress((void**)&wvtl, g_wvtl);
    cudaGetSymbolAddress((void**)&woth, g_woth); cudaGetSymbolAddress((void**)&wotl, g_wotl);
    cudaGetSymbolAddress((void**)&qhi, g_qhi);   cudaGetSymbolAddress((void**)&qlo, g_qlo);
    cudaGetSymbolAddress((void**)&khi, g_khi);   cudaGetSymbolAddress((void**)&klo, g_klo);
    cudaGetSymbolAddress((void**)&vthi, g_vthi); cudaGetSymbolAddress((void**)&vtlo, g_vtlo);
    cudaGetSymbolAddress((void**)&phi, g_phi);   cudaGetSymbolAddress((void**)&plo, g_plo);
    cudaGetSymbolAddress((void**)&aohi, g_aohi); cudaGetSymbolAddress((void**)&aolo, g_aolo);
    cudaGetSymbolAddress((void**)&S, g_S);

    const size_t sQ = (size_t)SEQ * DIM;
    const size_t sV = (size_t)DIM * SEQ;
    const size_t sS = (size_t)SEQ * SEQ;

    // 1) split x; transpose+split weights
    split_kernel<<<(unsigned)((RXD / 4 + 255) / 256), 256>>>(x, xhi, xlo, RXD / 4);
    dim3 tb(32, 8), tg(DIM / 32, DIM / 32);
    transpose_split<<<tg, tb>>>(Wq, wqth, wqtl);
    transpose_split<<<tg, tb>>>(Wk, wkth, wktl);
    transpose_split<<<tg, tb>>>(Wv, wvth, wvtl);
    transpose_split<<<tg, tb>>>(Wo, woth, wotl);

    // 2) projections (M=8192, N=1024, K=1024)
    dim3 gProj(DIM / 128, (BATCH * SEQ) / 128, 1);
    hm_gemm<1,0><<<gProj, TCN, SMEM_B>>>(xhi, xlo, wqth, wqtl, nullptr, qhi, qlo,
                                         DIM, DIM, 0, 0, 0);
    hm_gemm<1,0><<<gProj, TCN, SMEM_B>>>(xhi, xlo, wkth, wktl, nullptr, khi, klo,
                                         DIM, DIM, 0, 0, 0);
    hm_gemm<2,0><<<gProj, TCN, SMEM_B>>>(xhi, xlo, wvth, wvtl, nullptr, vthi, vtlo,
                                         DIM, DIM, 0, 0, 0);

    // 3) scores = Q @ K^T, per batch, lower-triangular tiles only
    dim3 gSc(SEQ / 128, SEQ / 128, BATCH);
    hm_gemm<0,1><<<gSc, TCN, SMEM_B>>>(qhi, qlo, khi, klo, S, nullptr, nullptr,
                                       SEQ, DIM, sQ, sQ, sS);

    // 4) softmax -> split P
    softmax_causal<<<dim3(SEQ, BATCH), 256>>>(S, phi, plo);

    // 5) AO = P @ V  (B operand = V^T, K-limited by causality)
    dim3 gPV(DIM / 128, SEQ / 128, BATCH);
    hm_gemm<1,2><<<gPV, TCN, SMEM_B>>>(phi, plo, vthi, vtlo, nullptr, aohi, aolo,
                                       DIM, SEQ, sS, sV, sQ);

    // 6) out = AO @ Wo
    dim3 gOut(DIM / 128, (BATCH * SEQ) / 128, 1);
    hm_gemm<0,0><<<gOut, TCN, SMEM_B>>>(aohi, aolo, woth, wotl, out, nullptr, nullptr,
                                        DIM, DIM, 0, 0, 0);
}

// round 5
// speedup vs baseline: 3.9204x; 1.4380x over previous
#include <cuda_runtime.h>
#include <cuda_fp16.h>
#include <cstdint>
#include <cstddef>

// ---------------------------------------------------------------------------
// Problem constants
// ---------------------------------------------------------------------------
#define BATCH 4
#define SEQ   2048
#define DIM   1024

// GEMM tiling: 128x128 CTA tile, 8 warps of 64x32, K chunks of 64 fp16.
#define KC     64
#define LDT    72                       // padded row stride in fp16 (144 B)
#define TILE_P (128 * LDT * 2)          // 18432 B per tile
#define NTILES 3                        // Ah, Bh, Bl
#define STG_B  (NTILES * TILE_P)        // 55296 B
#define NS     3                        // pipeline stages
#define SMEM_B (NS * STG_B)             // 165888 B
#define TCN    256

// ---------------------------------------------------------------------------
// PTX helpers (base sm_103 ISA: cp.async, ldmatrix, mma.sync)
// ---------------------------------------------------------------------------
__device__ __forceinline__ uint32_t smem_u32(const void* p) {
    uint32_t a;
    asm("{ .reg .u64 t; cvta.to.shared.u64 t, %1; cvt.u32.u64 %0, t; }"
        : "=r"(a) : "l"(p));
    return a;
}
__device__ __forceinline__ void cpa16(uint32_t dst, const void* src) {
    asm volatile("cp.async.cg.shared.global [%0], [%1], 16;"
                 :: "r"(dst), "l"(src));
}
__device__ __forceinline__ void cpa_commit() {
    asm volatile("cp.async.commit_group;");
}
__device__ __forceinline__ void ldm_x4(uint32_t* r, uint32_t addr) {
    asm volatile("ldmatrix.sync.aligned.m8n8.x4.shared.b16 {%0,%1,%2,%3}, [%4];"
                 : "=r"(r[0]), "=r"(r[1]), "=r"(r[2]), "=r"(r[3]) : "r"(addr));
}
__device__ __forceinline__ void mma16816(float* d, const uint32_t* a,
                                         uint32_t b0, uint32_t b1) {
    asm volatile(
        "mma.sync.aligned.m16n8k16.row.col.f32.f16.f16.f32 "
        "{%0,%1,%2,%3}, {%4,%5,%6,%7}, {%8,%9}, {%0,%1,%2,%3};"
        : "+f"(d[0]), "+f"(d[1]), "+f"(d[2]), "+f"(d[3])
        : "r"(a[0]), "r"(a[1]), "r"(a[2]), "r"(a[3]), "r"(b0), "r"(b1));
}

// fp16 hi/lo split of a float pair -> packed half2 words
__device__ __forceinline__ void split_pack2h(float a, float b,
                                             uint32_t& hp, uint32_t& lp) {
    __half ha = __float2half_rn(a), hb = __float2half_rn(b);
    __half la = __float2half_rn(a - __half2float(ha));
    __half lb = __float2half_rn(b - __half2float(hb));
    hp = (uint32_t)__half_as_ushort(ha) | ((uint32_t)__half_as_ushort(hb) << 16);
    lp = (uint32_t)__half_as_ushort(la) | ((uint32_t)__half_as_ushort(lb) << 16);
}
__device__ __forceinline__ uint32_t pack2h(float a, float b) {
    __half ha = __float2half_rn(a), hb = __float2half_rn(b);
    return (uint32_t)__half_as_ushort(ha) | ((uint32_t)__half_as_ushort(hb) << 16);
}

// ---------------------------------------------------------------------------
// Device scratch
// ---------------------------------------------------------------------------
#define RXD ((size_t)BATCH * SEQ * DIM)
#define RSS ((size_t)BATCH * SEQ * SEQ)
__device__ __half g_xh[RXD];                         // x hi (A-side)
__device__ __half g_wqkvth[3 * DIM * DIM], g_wqkvtl[3 * DIM * DIM];
__device__ __half g_woth[DIM * DIM], g_wotl[DIM * DIM];
__device__ __half g_qkh[(size_t)BATCH * SEQ * 2 * DIM];  // Q|K hi, [8192][2048]
__device__ __half g_qkl[(size_t)BATCH * SEQ * 2 * DIM];  // lo (K region used)
__device__ __half g_vth[RXD], g_vtl[RXD];            // V^T [B][DV][SEQ]
__device__ float  g_S[RSS];
__device__ __half g_ph[RSS];                         // P hi (A-side)
__device__ __half g_aoh[RXD];                        // AO hi (A-side)

// ---------------------------------------------------------------------------
// Async tile load: 128 rows x 64 fp16 (K-major) -> padded smem (stride LDT)
// ---------------------------------------------------------------------------
__device__ __forceinline__ void load_tile_async(uint32_t base,
                                                const __half* __restrict__ gp,
                                                int ld, int tid) {
    #pragma unroll
    for (int i = 0; i < 4; i++) {
        int idx = i * TCN + tid;
        int row = idx >> 3;
        int c16 = idx & 7;
        cpa16(base + row * (LDT * 2) + c16 * 16,
              gp + (size_t)row * ld + c16 * 8);
    }
}

// ---------------------------------------------------------------------------
// fp16 asymmetric 2-pass GEMM: C = Ah[M,K] @ (Bh+Bl)[N,K]^T
// MODE: 0 = fp32 out, 1 = half hi out (+lo where n>=lo_start),
//       3 = fused QKV (n<2048 normal hi(+lo for K region), n>=2048 V^T out)
// CAUSAL: 0 none, 1 skip tiles above diagonal, 2 K-limit
// ---------------------------------------------------------------------------
template<int MODE, int CAUSAL>
__global__ __launch_bounds__(TCN)
void hm2(const __half* __restrict__ A,
         const __half* __restrict__ Bh, const __half* __restrict__ Bl,
         float* __restrict__ C32, __half* __restrict__ Chi,
         __half* __restrict__ Clo,
         __half* __restrict__ Vth, __half* __restrict__ Vtl,
         int Nld, int ldA, int ldB, int Kdim, int lo_start,
         size_t sA, size_t sB, size_t sC)
{
    if (CAUSAL == 1 && blockIdx.x > blockIdx.y) return;

    const int row0 = blockIdx.y * 128;
    const int col0 = blockIdx.x * 128;
    const size_t zb = blockIdx.z;

    extern __shared__ char smem[];
    const uint32_t sb = smem_u32(smem);
    const int tid  = threadIdx.x;
    const int wid  = tid >> 5;
    const int lane = tid & 31;
    const int warp_m = wid >> 2;
    const int warp_n = wid & 3;
    const int gq = lane >> 2;
    const int tq = lane & 3;

    int kEnd = Kdim;
    if (CAUSAL == 2) {
        int lim = (blockIdx.y + 1) * 128;
        if (lim < kEnd) kEnd = lim;
    }
    const int nChunks = kEnd / KC;

    const __half* pA  = A  + zb * sA + (size_t)row0 * ldA;
    const __half* pBh = Bh + zb * sB + (size_t)col0 * ldB;
    const __half* pBl = Bl + zb * sB + (size_t)col0 * ldB;

    const int a_r  = lane & 15;
    const int a_kq = (lane >> 4) << 3;
    const int b_r  = (lane & 7) + ((lane >= 16) ? 8 : 0);
    const int b_kq = ((lane >> 3) & 1) << 3;

    float acc[4][4][4];
    #pragma unroll
    for (int i = 0; i < 4; i++)
        #pragma unroll
        for (int j = 0; j < 4; j++)
            #pragma unroll
            for (int q = 0; q < 4; q++) acc[i][j][q] = 0.0f;

    // prologue: prefetch NS-1 chunks (always commit NS-1 groups)
    #pragma unroll
    for (int s = 0; s < NS - 1; s++) {
        if (s < nChunks) {
            const uint32_t st = sb + s * STG_B;
            const int k0 = s * KC;
            load_tile_async(st,              pA  + k0, ldA, tid);
            load_tile_async(st + TILE_P,     pBh + k0, ldB, tid);
            load_tile_async(st + 2 * TILE_P, pBl + k0, ldB, tid);
        }
        cpa_commit();
    }

    for (int c = 0; c < nChunks; c++) {
        asm volatile("cp.async.wait_group %0;" :: "n"(NS - 2));
        __syncthreads();

        const uint32_t st = sb + (c % NS) * STG_B;
        #pragma unroll
        for (int ks = 0; ks < 4; ks++) {
            const int k0 = ks * 16;
            uint32_t ah[4][4], bh[2][4], bl[2][4];
            #pragma unroll
            for (int mb = 0; mb < 4; mb++) {
                const uint32_t aoff =
                    (warp_m * 64 + mb * 16 + a_r) * (LDT * 2) + (k0 + a_kq) * 2;
                ldm_x4(ah[mb], st + aoff);
            }
            #pragma unroll
            for (int nh = 0; nh < 2; nh++) {
                const uint32_t boff =
                    (warp_n * 32 + nh * 16 + b_r) * (LDT * 2) + (k0 + b_kq) * 2;
                ldm_x4(bh[nh], st + TILE_P + boff);
                ldm_x4(bl[nh], st + 2 * TILE_P + boff);
            }
            #pragma unroll
            for (int mb = 0; mb < 4; mb++) {
                #pragma unroll
                for (int nb = 0; nb < 4; nb++) {
                    const int nh = nb >> 1, p = (nb & 1) * 2;
                    mma16816(acc[mb][nb], ah[mb], bh[nh][p], bh[nh][p + 1]);
                    mma16816(acc[mb][nb], ah[mb], bl[nh][p], bl[nh][p + 1]);
                }
            }
        }
        __syncthreads();

        // prefetch chunk c + NS - 1 into the stage just freed
        const int cn = c + NS - 1;
        if (cn < nChunks) {
            const uint32_t stn = sb + (cn % NS) * STG_B;
            const int k0 = cn * KC;
            load_tile_async(stn,              pA  + k0, ldA, tid);
            load_tile_async(stn + TILE_P,     pBh + k0, ldB, tid);
            load_tile_async(stn + 2 * TILE_P, pBl + k0, ldB, tid);
        }
        cpa_commit();
    }

    // ---------------- Epilogue ----------------
    const bool vregion = (MODE == 3) && (col0 >= 2048);
    if (!vregion) {
        #pragma unroll
        for (int mb = 0; mb < 4; mb++) {
            const int m = row0 + warp_m * 64 + mb * 16 + gq;
            #pragma unroll
            for (int nb = 0; nb < 4; nb++) {
                const int n = col0 + warp_n * 32 + nb * 8 + tq * 2;
                const float* cc = acc[mb][nb];
                if (MODE == 0) {
                    float* d0 = C32 + zb * sC + (size_t)m * Nld + n;
                    float* d1 = C32 + zb * sC + (size_t)(m + 8) * Nld + n;
                    *reinterpret_cast<float2*>(d0) = make_float2(cc[0], cc[1]);
                    *reinterpret_cast<float2*>(d1) = make_float2(cc[2], cc[3]);
                } else {
                    size_t o0 = zb * sC + (size_t)m * Nld + n;
                    size_t o1 = zb * sC + (size_t)(m + 8) * Nld + n;
                    if (n >= lo_start) {
                        uint32_t hp, lp;
                        split_pack2h(cc[0], cc[1], hp, lp);
                        *reinterpret_cast<uint32_t*>(Chi + o0) = hp;
                        *reinterpret_cast<uint32_t*>(Clo + o0) = lp;
                        split_pack2h(cc[2], cc[3], hp, lp);
                        *reinterpret_cast<uint32_t*>(Chi + o1) = hp;
                        *reinterpret_cast<uint32_t*>(Clo + o1) = lp;
                    } else {
                        *reinterpret_cast<uint32_t*>(Chi + o0) = pack2h(cc[0], cc[1]);
                        *reinterpret_cast<uint32_t*>(Chi + o1) = pack2h(cc[2], cc[3]);
                    }
                }
            }
        }
    } else {
        // V^T region: transpose through smem, write hi+lo (B-side operand)
        float* smt = reinterpret_cast<float*>(smem);   // [128][129]
        __syncthreads();
        #pragma unroll
        for (int mb = 0; mb < 4; mb++) {
            const int m = warp_m * 64 + mb * 16 + gq;
            #pragma unroll
            for (int nb = 0; nb < 4; nb++) {
                const int n = warp_n * 32 + nb * 8 + tq * 2;
                const float* cc = acc[mb][nb];
                smt[m * 129 + n]           = cc[0];
                smt[m * 129 + n + 1]       = cc[1];
                smt[(m + 8) * 129 + n]     = cc[2];
                smt[(m + 8) * 129 + n + 1] = cc[3];
            }
        }
        __syncthreads();
        const int b  = row0 >> 11;
        const int s0 = row0 & (SEQ - 1);
        const int nl = tid >> 1;
        const int sh = (tid & 1) * 64;
        const size_t base = (size_t)b * DIM * SEQ +
                            (size_t)(col0 - 2048 + nl) * SEQ + s0 + sh;
        #pragma unroll
        for (int u = 0; u < 64; u += 2) {
            uint32_t hp, lp;
            split_pack2h(smt[(sh + u) * 129 + nl], smt[(sh + u + 1) * 129 + nl],
                         hp, lp);
            *reinterpret_cast<uint32_t*>(Vth + base + u) = hp;
            *reinterpret_cast<uint32_t*>(Vtl + base + u) = lp;
        }
    }
}

// ---------------------------------------------------------------------------
// Preprocess: x fp32 -> fp16 hi only (A-side operand)
// ---------------------------------------------------------------------------
__global__ void split_x(const float* __restrict__ in,
                        __half* __restrict__ xh, size_t n4)
{
    size_t i = (size_t)blockIdx.x * blockDim.x + threadIdx.x;
    if (i >= n4) return;
    float4 v = reinterpret_cast<const float4*>(in)[i];
    uint2 o;
    o.x = pack2h(v.x, v.y);
    o.y = pack2h(v.z, v.w);
    reinterpret_cast<uint2*>(xh)[i] = o;
}

// W [K][N] fp32 -> W^T hi/lo fp16; z selects Wq/Wk/Wv (into concat wqkvt)
// or Wo (into wot).
__global__ void transpose_qkvo(const float* __restrict__ Wq,
                               const float* __restrict__ Wk,
                               const float* __restrict__ Wv,
                               const float* __restrict__ Wo,
                               __half* __restrict__ qkvh,
                               __half* __restrict__ qkvl,
                               __half* __restrict__ woh,
                               __half* __restrict__ wol)
{
    __shared__ float t[32][33];
    const int z = blockIdx.z;
    const float* in = (z == 0) ? Wq : (z == 1) ? Wk : (z == 2) ? Wv : Wo;
    __half* dh = (z < 3) ? qkvh + (size_t)z * DIM * DIM : woh;
    __half* dl = (z < 3) ? qkvl + (size_t)z * DIM * DIM : wol;

    const int bx = blockIdx.x * 32, by = blockIdx.y * 32;
    const int x = threadIdx.x, y = threadIdx.y;   // 32 x 8
    #pragma unroll
    for (int i = 0; i < 32; i += 8)
        t[y + i][x] = in[(size_t)(by + y + i) * DIM + bx + x];
    __syncthreads();
    #pragma unroll
    for (int i = 0; i < 32; i += 8) {
        float v = t[x][y + i];
        __half h = __float2half_rn(v);
        size_t o = (size_t)(bx + y + i) * DIM + by + x;
        dh[o] = h;
        dl[o] = __float2half_rn(v - __half2float(h));
    }
}

// ---------------------------------------------------------------------------
// Causal softmax: fp32 S (lower triangle) -> fp16 P hi; zeros only the
// in-diagonal-tile upper wedge (the only masked entries the PV GEMM reads).
// ---------------------------------------------------------------------------
__global__ void softmax_causal(const float* __restrict__ Sbuf,
                               __half* __restrict__ Ph)
{
    const int i = blockIdx.x;
    const int b = blockIdx.y;
    const size_t off = ((size_t)b * SEQ + i) * SEQ;
    const float* row = Sbuf + off;
    const int n = i + 1;
    const float scale = 0.03125f;   // 1/sqrt(1024)

    __shared__ float red[256];
    const int tid = threadIdx.x;

    float m = -3.402823466e+38f;
    for (int j = tid; j < n; j += 256) m = fmaxf(m, row[j]);
    red[tid] = m;
    __syncthreads();
    #pragma unroll
    for (int s = 128; s > 0; s >>= 1) {
        if (tid < s) red[tid] = fmaxf(red[tid], red[tid + s]);
        __syncthreads();
    }
    const float mx = red[0] * scale;
    __syncthreads();

    float sum = 0.0f;
    for (int j = tid; j < n; j += 256) sum += __expf(row[j] * scale - mx);
    red[tid] = sum;
    __syncthreads();
    #pragma unroll
    for (int s = 128; s > 0; s >>= 1) {
        if (tid < s) red[tid] += red[tid + s];
        __syncthreads();
    }
    const float inv = 1.0f / red[0];

    for (int j = tid; j < n; j += 256)
        Ph[off + j] = __float2half_rn(__expf(row[j] * scale - mx) * inv);

    // zero the rest of the diagonal 128-tile only
    const int tileEnd = ((i >> 7) + 1) << 7;
    for (int j = n + tid; j < tileEnd; j += 256)
        Ph[off + j] = __ushort_as_half((unsigned short)0);
}

// ---------------------------------------------------------------------------
// Launch
// ---------------------------------------------------------------------------
extern "C" void kernel_launch(void* const* d_in, const int* in_sizes, int n_in,
                              void* d_out, int out_size)
{
    const float* x  = (const float*)d_in[0];
    const float* Wq = (const float*)d_in[1];
    const float* Wk = (const float*)d_in[2];
    const float* Wv = (const float*)d_in[3];
    const float* Wo = (const float*)d_in[4];
    float* out = (float*)d_out;

    cudaFuncSetAttribute(hm2<3,0>, cudaFuncAttributeMaxDynamicSharedMemorySize, SMEM_B);
    cudaFuncSetAttribute(hm2<0,1>, cudaFuncAttributeMaxDynamicSharedMemorySize, SMEM_B);
    cudaFuncSetAttribute(hm2<1,2>, cudaFuncAttributeMaxDynamicSharedMemorySize, SMEM_B);
    cudaFuncSetAttribute(hm2<0,0>, cudaFuncAttributeMaxDynamicSharedMemorySize, SMEM_B);

    __half *xh, *qkvh, *qkvl, *woh, *wol, *qkh, *qkl, *vth, *vtl, *ph, *aoh;
    float* S;
    cudaGetSymbolAddress((void**)&xh, g_xh);
    cudaGetSymbolAddress((void**)&qkvh, g_wqkvth);
    cudaGetSymbolAddress((void**)&qkvl, g_wqkvtl);
    cudaGetSymbolAddress((void**)&woh, g_woth);
    cudaGetSymbolAddress((void**)&wol, g_wotl);
    cudaGetSymbolAddress((void**)&qkh, g_qkh);
    cudaGetSymbolAddress((void**)&qkl, g_qkl);
    cudaGetSymbolAddress((void**)&vth, g_vth);
    cudaGetSymbolAddress((void**)&vtl, g_vtl);
    cudaGetSymbolAddress((void**)&ph, g_ph);
    cudaGetSymbolAddress((void**)&aoh, g_aoh);
    cudaGetSymbolAddress((void**)&S, g_S);

    const size_t sQK = (size_t)SEQ * 2 * DIM;   // per-batch Q|K row block
    const size_t sV  = (size_t)DIM * SEQ;
    const size_t sS  = (size_t)SEQ * SEQ;

    // 1) x -> fp16 hi
    split_x<<<(unsigned)((RXD / 4 + 255) / 256), 256>>>(x, xh, RXD / 4);

    // 2) weights: transpose + hi/lo split (Wq|Wk|Wv concat, Wo separate)
    transpose_qkvo<<<dim3(DIM / 32, DIM / 32, 4), dim3(32, 8)>>>(
        Wq, Wk, Wv, Wo, qkvh, qkvl, woh, wol);

    // 3) fused QKV projection: [8192,1024] @ [1024,3072]
    //    n<1024: Q hi; 1024<=n<2048: K hi+lo; n>=2048: V^T hi+lo
    hm2<3,0><<<dim3(3 * DIM / 128, BATCH * SEQ / 128, 1), TCN, SMEM_B>>>(
        xh, qkvh, qkvl, nullptr, qkh, qkl, vth, vtl,
        2 * DIM, DIM, DIM, DIM, DIM, 0, 0, 0);

    // 4) scores = Q @ K^T per batch (lower-triangular tiles)
    hm2<0,1><<<dim3(SEQ / 128, SEQ / 128, BATCH), TCN, SMEM_B>>>(
        qkh, qkh + DIM, qkl + DIM, S, nullptr, nullptr, nullptr, nullptr,
        SEQ, 2 * DIM, 2 * DIM, DIM, 0, sQK, sQK, sS);

    // 5) softmax -> P hi
    softmax_causal<<<dim3(SEQ, BATCH), 256>>>(S, ph);

    // 6) AO = P @ V (B = V^T hi+lo, K-limited)
    hm2<1,2><<<dim3(DIM / 128, SEQ / 128, BATCH), TCN, SMEM_B>>>(
        ph, vth, vtl, nullptr, aoh, nullptr, nullptr, nullptr,
        DIM, SEQ, SEQ, SEQ, 1 << 30, sS, sV, (size_t)SEQ * DIM);

    // 7) out = AO @ Wo
    hm2<0,0><<<dim3(DIM / 128, BATCH * SEQ / 128, 1), TCN, SMEM_B>>>(
        aoh, woh, wol, out, nullptr, nullptr, nullptr, nullptr,
        DIM, DIM, DIM, DIM, 0, 0, 0, 0);
}

// round 6
// speedup vs baseline: 4.2091x; 1.0737x over previous
#include <cuda_runtime.h>
#include <cuda_fp16.h>
#include <cstdint>
#include <cstddef>

// ---------------------------------------------------------------------------
// Problem constants
// ---------------------------------------------------------------------------
#define BATCH 4
#define SEQ   2048
#define DIM   1024

// GEMM tiling: 128x128 CTA tile, 8 warps of 64x32, K chunks of 64 fp16.
#define KC     64
#define LDT    72                       // padded row stride in fp16 (144 B)
#define TILE_P (128 * LDT * 2)          // 18432 B per tile
#define NTILES 3                        // Ah, Bh, Bl
#define STG_B  (NTILES * TILE_P)        // 55296 B
#define NS     2                        // pipeline stages (2 => 2 CTAs/SM)
#define SMEM_B (NS * STG_B)             // 110592 B
#define TCN    256

// ---------------------------------------------------------------------------
// PTX helpers (base sm_103 ISA: cp.async, ldmatrix, mma.sync)
// ---------------------------------------------------------------------------
__device__ __forceinline__ uint32_t smem_u32(const void* p) {
    uint32_t a;
    asm("{ .reg .u64 t; cvta.to.shared.u64 t, %1; cvt.u32.u64 %0, t; }"
        : "=r"(a) : "l"(p));
    return a;
}
__device__ __forceinline__ void cpa16(uint32_t dst, const void* src) {
    asm volatile("cp.async.cg.shared.global [%0], [%1], 16;"
                 :: "r"(dst), "l"(src));
}
__device__ __forceinline__ void cpa_commit() {
    asm volatile("cp.async.commit_group;");
}
__device__ __forceinline__ void ldm_x4(uint32_t* r, uint32_t addr) {
    asm volatile("ldmatrix.sync.aligned.m8n8.x4.shared.b16 {%0,%1,%2,%3}, [%4];"
                 : "=r"(r[0]), "=r"(r[1]), "=r"(r[2]), "=r"(r[3]) : "r"(addr));
}
__device__ __forceinline__ void mma16816(float* d, const uint32_t* a,
                                         uint32_t b0, uint32_t b1) {
    asm volatile(
        "mma.sync.aligned.m16n8k16.row.col.f32.f16.f16.f32 "
        "{%0,%1,%2,%3}, {%4,%5,%6,%7}, {%8,%9}, {%0,%1,%2,%3};"
        : "+f"(d[0]), "+f"(d[1]), "+f"(d[2]), "+f"(d[3])
        : "r"(a[0]), "r"(a[1]), "r"(a[2]), "r"(a[3]), "r"(b0), "r"(b1));
}

// fp16 hi/lo split of a float pair -> packed half2 words
__device__ __forceinline__ void split_pack2h(float a, float b,
                                             uint32_t& hp, uint32_t& lp) {
    __half ha = __float2half_rn(a), hb = __float2half_rn(b);
    __half la = __float2half_rn(a - __half2float(ha));
    __half lb = __float2half_rn(b - __half2float(hb));
    hp = (uint32_t)__half_as_ushort(ha) | ((uint32_t)__half_as_ushort(hb) << 16);
    lp = (uint32_t)__half_as_ushort(la) | ((uint32_t)__half_as_ushort(lb) << 16);
}
__device__ __forceinline__ uint32_t pack2h(float a, float b) {
    __half ha = __float2half_rn(a), hb = __float2half_rn(b);
    return (uint32_t)__half_as_ushort(ha) | ((uint32_t)__half_as_ushort(hb) << 16);
}

// ---------------------------------------------------------------------------
// Device scratch
// ---------------------------------------------------------------------------
#define RXD ((size_t)BATCH * SEQ * DIM)
#define RSS ((size_t)BATCH * SEQ * SEQ)
__device__ __half g_xh[RXD];                         // x hi (A-side)
__device__ __half g_wqkvth[3 * DIM * DIM], g_wqkvtl[3 * DIM * DIM];
__device__ __half g_woth[DIM * DIM], g_wotl[DIM * DIM];
__device__ __half g_qkh[(size_t)BATCH * SEQ * 2 * DIM];  // Q|K hi, [8192][2048]
__device__ __half g_qkl[(size_t)BATCH * SEQ * 2 * DIM];  // lo (K region used)
__device__ __half g_vth[RXD], g_vtl[RXD];            // V^T [B][DV][SEQ]
__device__ float  g_S[RSS];
__device__ __half g_ph[RSS];                         // P hi (A-side)
__device__ __half g_aoh[RXD];                        // AO hi (A-side)

// ---------------------------------------------------------------------------
// Async tile load: 128 rows x 64 fp16 (K-major) -> padded smem (stride LDT)
// ---------------------------------------------------------------------------
__device__ __forceinline__ void load_tile_async(uint32_t base,
                                                const __half* __restrict__ gp,
                                                int ld, int tid) {
    #pragma unroll
    for (int i = 0; i < 4; i++) {
        int idx = i * TCN + tid;
        int row = idx >> 3;
        int c16 = idx & 7;
        cpa16(base + row * (LDT * 2) + c16 * 16,
              gp + (size_t)row * ld + c16 * 8);
    }
}

// ---------------------------------------------------------------------------
// fp16 asymmetric 2-pass GEMM: C = Ah[M,K] @ (Bh+Bl)[N,K]^T
// MODE: 0 = fp32 out, 1 = half hi out (+lo where n>=lo_start),
//       3 = fused QKV (n<2048 normal hi(+lo for K region), n>=2048 V^T out)
// CAUSAL: 0 none, 1 skip tiles above diagonal, 2 K-limit
// ---------------------------------------------------------------------------
template<int MODE, int CAUSAL>
__global__ __launch_bounds__(TCN, 2)
void hm2(const __half* __restrict__ A,
         const __half* __restrict__ Bh, const __half* __restrict__ Bl,
         float* __restrict__ C32, __half* __restrict__ Chi,
         __half* __restrict__ Clo,
         __half* __restrict__ Vth, __half* __restrict__ Vtl,
         int Nld, int ldA, int ldB, int Kdim, int lo_start,
         size_t sA, size_t sB, size_t sC)
{
    if (CAUSAL == 1 && blockIdx.x > blockIdx.y) return;

    const int row0 = blockIdx.y * 128;
    const int col0 = blockIdx.x * 128;
    const size_t zb = blockIdx.z;

    extern __shared__ char smem[];
    const uint32_t sb = smem_u32(smem);
    const int tid  = threadIdx.x;
    const int wid  = tid >> 5;
    const int lane = tid & 31;
    const int warp_m = wid >> 2;
    const int warp_n = wid & 3;
    const int gq = lane >> 2;
    const int tq = lane & 3;

    int kEnd = Kdim;
    if (CAUSAL == 2) {
        int lim = (blockIdx.y + 1) * 128;
        if (lim < kEnd) kEnd = lim;
    }
    const int nChunks = kEnd / KC;

    const __half* pA  = A  + zb * sA + (size_t)row0 * ldA;
    const __half* pBh = Bh + zb * sB + (size_t)col0 * ldB;
    const __half* pBl = Bl + zb * sB + (size_t)col0 * ldB;

    const int a_r  = lane & 15;
    const int a_kq = (lane >> 4) << 3;
    const int b_r  = (lane & 7) + ((lane >= 16) ? 8 : 0);
    const int b_kq = ((lane >> 3) & 1) << 3;

    // per-warp smem byte offsets (within a stage)
    const uint32_t aoff0 = (warp_m * 64 + a_r) * (LDT * 2) + a_kq * 2;
    const uint32_t boff0 = (warp_n * 32 + b_r) * (LDT * 2) + b_kq * 2;

    float acc[4][4][4];
    #pragma unroll
    for (int i = 0; i < 4; i++)
        #pragma unroll
        for (int j = 0; j < 4; j++)
            #pragma unroll
            for (int q = 0; q < 4; q++) acc[i][j][q] = 0.0f;

    // prologue: prefetch chunk 0 into stage 0
    {
        load_tile_async(sb,              pA,  ldA, tid);
        load_tile_async(sb + TILE_P,     pBh, ldB, tid);
        load_tile_async(sb + 2 * TILE_P, pBl, ldB, tid);
        cpa_commit();
    }

    for (int c = 0; c < nChunks; c++) {
        if (c + 1 < nChunks) {
            const uint32_t stn = sb + ((c + 1) & 1) * STG_B;
            const int k0 = (c + 1) * KC;
            load_tile_async(stn,              pA  + k0, ldA, tid);
            load_tile_async(stn + TILE_P,     pBh + k0, ldB, tid);
            load_tile_async(stn + 2 * TILE_P, pBl + k0, ldB, tid);
            cpa_commit();
            asm volatile("cp.async.wait_group 1;");
        } else {
            asm volatile("cp.async.wait_group 0;");
        }
        __syncthreads();

        const uint32_t st = sb + (c & 1) * STG_B;
        #pragma unroll
        for (int ks = 0; ks < 4; ks++) {
            const uint32_t kb = ks * 32;      // 16 fp16 = 32 bytes
            uint32_t ah[4][4], bh[2][4], bl[2][4];
            #pragma unroll
            for (int mb = 0; mb < 4; mb++)
                ldm_x4(ah[mb], st + aoff0 + mb * 16 * (LDT * 2) + kb);
            #pragma unroll
            for (int nh = 0; nh < 2; nh++) {
                const uint32_t bo = boff0 + nh * 16 * (LDT * 2) + kb;
                ldm_x4(bh[nh], st + TILE_P + bo);
                ldm_x4(bl[nh], st + 2 * TILE_P + bo);
            }
            #pragma unroll
            for (int mb = 0; mb < 4; mb++) {
                #pragma unroll
                for (int nb = 0; nb < 4; nb++) {
                    const int nh = nb >> 1, p = (nb & 1) * 2;
                    mma16816(acc[mb][nb], ah[mb], bh[nh][p], bh[nh][p + 1]);
                    mma16816(acc[mb][nb], ah[mb], bl[nh][p], bl[nh][p + 1]);
                }
            }
        }
        __syncthreads();
    }

    // ---------------- Epilogue ----------------
    const bool vregion = (MODE == 3) && (col0 >= 2048);
    if (!vregion) {
        #pragma unroll
        for (int mb = 0; mb < 4; mb++) {
            const int m = row0 + warp_m * 64 + mb * 16 + gq;
            #pragma unroll
            for (int nb = 0; nb < 4; nb++) {
                const int n = col0 + warp_n * 32 + nb * 8 + tq * 2;
                const float* cc = acc[mb][nb];
                if (MODE == 0) {
                    float* d0 = C32 + zb * sC + (size_t)m * Nld + n;
                    float* d1 = C32 + zb * sC + (size_t)(m + 8) * Nld + n;
                    *reinterpret_cast<float2*>(d0) = make_float2(cc[0], cc[1]);
                    *reinterpret_cast<float2*>(d1) = make_float2(cc[2], cc[3]);
                } else {
                    size_t o0 = zb * sC + (size_t)m * Nld + n;
                    size_t o1 = zb * sC + (size_t)(m + 8) * Nld + n;
                    if (n >= lo_start) {
                        uint32_t hp, lp;
                        split_pack2h(cc[0], cc[1], hp, lp);
                        *reinterpret_cast<uint32_t*>(Chi + o0) = hp;
                        *reinterpret_cast<uint32_t*>(Clo + o0) = lp;
                        split_pack2h(cc[2], cc[3], hp, lp);
                        *reinterpret_cast<uint32_t*>(Chi + o1) = hp;
                        *reinterpret_cast<uint32_t*>(Clo + o1) = lp;
                    } else {
                        *reinterpret_cast<uint32_t*>(Chi + o0) = pack2h(cc[0], cc[1]);
                        *reinterpret_cast<uint32_t*>(Chi + o1) = pack2h(cc[2], cc[3]);
                    }
                }
            }
        }
    } else {
        // V^T region: transpose through smem, write hi+lo (B-side operand)
        float* smt = reinterpret_cast<float*>(smem);   // [128][129]
        __syncthreads();
        #pragma unroll
        for (int mb = 0; mb < 4; mb++) {
            const int m = warp_m * 64 + mb * 16 + gq;
            #pragma unroll
            for (int nb = 0; nb < 4; nb++) {
                const int n = warp_n * 32 + nb * 8 + tq * 2;
                const float* cc = acc[mb][nb];
                smt[m * 129 + n]           = cc[0];
                smt[m * 129 + n + 1]       = cc[1];
                smt[(m + 8) * 129 + n]     = cc[2];
                smt[(m + 8) * 129 + n + 1] = cc[3];
            }
        }
        __syncthreads();
        const int b  = row0 >> 11;
        const int s0 = row0 & (SEQ - 1);
        const int nl = tid >> 1;
        const int sh = (tid & 1) * 64;
        const size_t base = (size_t)b * DIM * SEQ +
                            (size_t)(col0 - 2048 + nl) * SEQ + s0 + sh;
        #pragma unroll
        for (int u = 0; u < 64; u += 2) {
            uint32_t hp, lp;
            split_pack2h(smt[(sh + u) * 129 + nl], smt[(sh + u + 1) * 129 + nl],
                         hp, lp);
            *reinterpret_cast<uint32_t*>(Vth + base + u) = hp;
            *reinterpret_cast<uint32_t*>(Vtl + base + u) = lp;
        }
    }
}

// ---------------------------------------------------------------------------
// Preprocess: x fp32 -> fp16 hi only (A-side operand)
// ---------------------------------------------------------------------------
__global__ void split_x(const float* __restrict__ in,
                        __half* __restrict__ xh, size_t n4)
{
    size_t i = (size_t)blockIdx.x * blockDim.x + threadIdx.x;
    if (i >= n4) return;
    float4 v = reinterpret_cast<const float4*>(in)[i];
    uint2 o;
    o.x = pack2h(v.x, v.y);
    o.y = pack2h(v.z, v.w);
    reinterpret_cast<uint2*>(xh)[i] = o;
}

// W [K][N] fp32 -> W^T hi/lo fp16; z selects Wq/Wk/Wv (into concat wqkvt)
// or Wo (into wot).
__global__ void transpose_qkvo(const float* __restrict__ Wq,
                               const float* __restrict__ Wk,
                               const float* __restrict__ Wv,
                               const float* __restrict__ Wo,
                               __half* __restrict__ qkvh,
                               __half* __restrict__ qkvl,
                               __half* __restrict__ woh,
                               __half* __restrict__ wol)
{
    __shared__ float t[32][33];
    const int z = blockIdx.z;
    const float* in = (z == 0) ? Wq : (z == 1) ? Wk : (z == 2) ? Wv : Wo;
    __half* dh = (z < 3) ? qkvh + (size_t)z * DIM * DIM : woh;
    __half* dl = (z < 3) ? qkvl + (size_t)z * DIM * DIM : wol;

    const int bx = blockIdx.x * 32, by = blockIdx.y * 32;
    const int x = threadIdx.x, y = threadIdx.y;   // 32 x 8
    #pragma unroll
    for (int i = 0; i < 32; i += 8)
        t[y + i][x] = in[(size_t)(by + y + i) * DIM + bx + x];
    __syncthreads();
    #pragma unroll
    for (int i = 0; i < 32; i += 8) {
        float v = t[x][y + i];
        __half h = __float2half_rn(v);
        size_t o = (size_t)(bx + y + i) * DIM + by + x;
        dh[o] = h;
        dl[o] = __float2half_rn(v - __half2float(h));
    }
}

// ---------------------------------------------------------------------------
// Causal softmax: fp32 S (lower triangle) -> fp16 P hi; zeros only the
// in-diagonal-tile upper wedge (the only masked entries the PV GEMM reads).
// ---------------------------------------------------------------------------
__global__ void softmax_causal(const float* __restrict__ Sbuf,
                               __half* __restrict__ Ph)
{
    const int i = blockIdx.x;
    const int b = blockIdx.y;
    const size_t off = ((size_t)b * SEQ + i) * SEQ;
    const float* row = Sbuf + off;
    const int n = i + 1;
    const float scale = 0.03125f;   // 1/sqrt(1024)

    __shared__ float red[256];
    const int tid = threadIdx.x;

    float m = -3.402823466e+38f;
    for (int j = tid; j < n; j += 256) m = fmaxf(m, row[j]);
    red[tid] = m;
    __syncthreads();
    #pragma unroll
    for (int s = 128; s > 0; s >>= 1) {
        if (tid < s) red[tid] = fmaxf(red[tid], red[tid + s]);
        __syncthreads();
    }
    const float mx = red[0] * scale;
    __syncthreads();

    float sum = 0.0f;
    for (int j = tid; j < n; j += 256) sum += __expf(row[j] * scale - mx);
    red[tid] = sum;
    __syncthreads();
    #pragma unroll
    for (int s = 128; s > 0; s >>= 1) {
        if (tid < s) red[tid] += red[tid + s];
        __syncthreads();
    }
    const float inv = 1.0f / red[0];

    for (int j = tid; j < n; j += 256)
        Ph[off + j] = __float2half_rn(__expf(row[j] * scale - mx) * inv);

    // zero the rest of the diagonal 128-tile only
    const int tileEnd = ((i >> 7) + 1) << 7;
    for (int j = n + tid; j < tileEnd; j += 256)
        Ph[off + j] = __ushort_as_half((unsigned short)0);
}

// ---------------------------------------------------------------------------
// Launch
// ---------------------------------------------------------------------------
extern "C" void kernel_launch(void* const* d_in, const int* in_sizes, int n_in,
                              void* d_out, int out_size)
{
    const float* x  = (const float*)d_in[0];
    const float* Wq = (const float*)d_in[1];
    const float* Wk = (const float*)d_in[2];
    const float* Wv = (const float*)d_in[3];
    const float* Wo = (const float*)d_in[4];
    float* out = (float*)d_out;

    cudaFuncSetAttribute(hm2<3,0>, cudaFuncAttributeMaxDynamicSharedMemorySize, SMEM_B);
    cudaFuncSetAttribute(hm2<0,1>, cudaFuncAttributeMaxDynamicSharedMemorySize, SMEM_B);
    cudaFuncSetAttribute(hm2<1,2>, cudaFuncAttributeMaxDynamicSharedMemorySize, SMEM_B);
    cudaFuncSetAttribute(hm2<0,0>, cudaFuncAttributeMaxDynamicSharedMemorySize, SMEM_B);

    __half *xh, *qkvh, *qkvl, *woh, *wol, *qkh, *qkl, *vth, *vtl, *ph, *aoh;
    float* S;
    cudaGetSymbolAddress((void**)&xh, g_xh);
    cudaGetSymbolAddress((void**)&qkvh, g_wqkvth);
    cudaGetSymbolAddress((void**)&qkvl, g_wqkvtl);
    cudaGetSymbolAddress((void**)&woh, g_woth);
    cudaGetSymbolAddress((void**)&wol, g_wotl);
    cudaGetSymbolAddress((void**)&qkh, g_qkh);
    cudaGetSymbolAddress((void**)&qkl, g_qkl);
    cudaGetSymbolAddress((void**)&vth, g_vth);
    cudaGetSymbolAddress((void**)&vtl, g_vtl);
    cudaGetSymbolAddress((void**)&ph, g_ph);
    cudaGetSymbolAddress((void**)&aoh, g_aoh);
    cudaGetSymbolAddress((void**)&S, g_S);

    const size_t sQK = (size_t)SEQ * 2 * DIM;   // per-batch Q|K row block
    const size_t sV  = (size_t)DIM * SEQ;
    const size_t sS  = (size_t)SEQ * SEQ;

    // 1) x -> fp16 hi
    split_x<<<(unsigned)((RXD / 4 + 255) / 256), 256>>>(x, xh, RXD / 4);

    // 2) weights: transpose + hi/lo split (Wq|Wk|Wv concat, Wo separate)
    transpose_qkvo<<<dim3(DIM / 32, DIM / 32, 4), dim3(32, 8)>>>(
        Wq, Wk, Wv, Wo, qkvh, qkvl, woh, wol);

    // 3) fused QKV projection: [8192,1024] @ [1024,3072]
    //    n<1024: Q hi; 1024<=n<2048: K hi+lo; n>=2048: V^T hi+lo
    hm2<3,0><<<dim3(3 * DIM / 128, BATCH * SEQ / 128, 1), TCN, SMEM_B>>>(
        xh, qkvh, qkvl, nullptr, qkh, qkl, vth, vtl,
        2 * DIM, DIM, DIM, DIM, DIM, 0, 0, 0);

    // 4) scores = Q @ K^T per batch (lower-triangular tiles)
    hm2<0,1><<<dim3(SEQ / 128, SEQ / 128, BATCH), TCN, SMEM_B>>>(
        qkh, qkh + DIM, qkl + DIM, S, nullptr, nullptr, nullptr, nullptr,
        SEQ, 2 * DIM, 2 * DIM, DIM, 0, sQK, sQK, sS);

    // 5) softmax -> P hi
    softmax_causal<<<dim3(SEQ, BATCH), 256>>>(S, ph);

    // 6) AO = P @ V (B = V^T hi+lo, K-limited)
    hm2<1,2><<<dim3(DIM / 128, SEQ / 128, BATCH), TCN, SMEM_B>>>(
        ph, vth, vtl, nullptr, aoh, nullptr, nullptr, nullptr,
        DIM, SEQ, SEQ, SEQ, 1 << 30, sS, sV, (size_t)SEQ * DIM);

    // 7) out = AO @ Wo
    hm2<0,0><<<dim3(DIM / 128, BATCH * SEQ / 128, 1), TCN, SMEM_B>>>(
        aoh, woh, wol, out, nullptr, nullptr, nullptr, nullptr,
        DIM, DIM, DIM, DIM, 0, 0, 0, 0);
}

// round 7
// speedup vs baseline: 4.2246x; 1.0037x over previous
#include <cuda_runtime.h>
#include <cuda_fp16.h>
#include <cstdint>
#include <cstddef>

// ---------------------------------------------------------------------------
// Problem constants
// ---------------------------------------------------------------------------
#define BATCH 4
#define SEQ   2048
#define DIM   1024

// GEMM tiling: 128x128 CTA tile, 4 warps of 64x64, K chunks of 64 fp16.
#define KC     64
#define LDT    72                       // padded row stride in fp16 (144 B)
#define TILE_P (128 * LDT * 2)          // 18432 B per tile
#define NTILES 3                        // Ah, Bh, Bl
#define STG_B  (NTILES * TILE_P)        // 55296 B
#define NS     2                        // pipeline stages (2 => 2 CTAs/SM)
#define SMEM_B (NS * STG_B)             // 110592 B
#define GT     128                      // threads per GEMM CTA (4 warps)

// ---------------------------------------------------------------------------
// PTX helpers (base sm_103 ISA: cp.async, ldmatrix, mma.sync)
// ---------------------------------------------------------------------------
__device__ __forceinline__ uint32_t smem_u32(const void* p) {
    uint32_t a;
    asm("{ .reg .u64 t; cvta.to.shared.u64 t, %1; cvt.u32.u64 %0, t; }"
        : "=r"(a) : "l"(p));
    return a;
}
__device__ __forceinline__ void cpa16(uint32_t dst, const void* src) {
    asm volatile("cp.async.cg.shared.global [%0], [%1], 16;"
                 :: "r"(dst), "l"(src));
}
__device__ __forceinline__ void cpa_commit() {
    asm volatile("cp.async.commit_group;");
}
__device__ __forceinline__ void ldm_x4(uint32_t* r, uint32_t addr) {
    asm volatile("ldmatrix.sync.aligned.m8n8.x4.shared.b16 {%0,%1,%2,%3}, [%4];"
                 : "=r"(r[0]), "=r"(r[1]), "=r"(r[2]), "=r"(r[3]) : "r"(addr));
}
__device__ __forceinline__ void mma16816(float* d, const uint32_t* a,
                                         uint32_t b0, uint32_t b1) {
    asm volatile(
        "mma.sync.aligned.m16n8k16.row.col.f32.f16.f16.f32 "
        "{%0,%1,%2,%3}, {%4,%5,%6,%7}, {%8,%9}, {%0,%1,%2,%3};"
        : "+f"(d[0]), "+f"(d[1]), "+f"(d[2]), "+f"(d[3])
        : "r"(a[0]), "r"(a[1]), "r"(a[2]), "r"(a[3]), "r"(b0), "r"(b1));
}

// fp16 hi/lo split of a float pair -> packed half2 words
__device__ __forceinline__ void split_pack2h(float a, float b,
                                             uint32_t& hp, uint32_t& lp) {
    __half ha = __float2half_rn(a), hb = __float2half_rn(b);
    __half la = __float2half_rn(a - __half2float(ha));
    __half lb = __float2half_rn(b - __half2float(hb));
    hp = (uint32_t)__half_as_ushort(ha) | ((uint32_t)__half_as_ushort(hb) << 16);
    lp = (uint32_t)__half_as_ushort(la) | ((uint32_t)__half_as_ushort(lb) << 16);
}
__device__ __forceinline__ uint32_t pack2h(float a, float b) {
    __half ha = __float2half_rn(a), hb = __float2half_rn(b);
    return (uint32_t)__half_as_ushort(ha) | ((uint32_t)__half_as_ushort(hb) << 16);
}

// ---------------------------------------------------------------------------
// Device scratch
// ---------------------------------------------------------------------------
#define RXD ((size_t)BATCH * SEQ * DIM)
#define RSS ((size_t)BATCH * SEQ * SEQ)
__device__ __half g_xh[RXD];                         // x hi (A-side)
__device__ __half g_wqkvth[3 * DIM * DIM], g_wqkvtl[3 * DIM * DIM];
__device__ __half g_woth[DIM * DIM], g_wotl[DIM * DIM];
__device__ __half g_qkh[(size_t)BATCH * SEQ * 2 * DIM];  // Q|K hi, [8192][2048]
__device__ __half g_qkl[(size_t)BATCH * SEQ * 2 * DIM];  // lo (K region used)
__device__ __half g_vth[RXD], g_vtl[RXD];            // V^T [B][DV][SEQ]
__device__ float  g_S[RSS];
__device__ __half g_ph[RSS];                         // P hi (A-side)
__device__ __half g_aoh[RXD];                        // AO hi (A-side)

// ---------------------------------------------------------------------------
// Async tile load: 128 rows x 64 fp16 (K-major) -> padded smem (stride LDT)
// ---------------------------------------------------------------------------
__device__ __forceinline__ void load_tile_async(uint32_t base,
                                                const __half* __restrict__ gp,
                                                int ld, int tid) {
    #pragma unroll
    for (int i = 0; i < 8; i++) {
        int idx = i * GT + tid;           // 0..1023
        int row = idx >> 3;
        int c16 = idx & 7;
        cpa16(base + row * (LDT * 2) + c16 * 16,
              gp + (size_t)row * ld + c16 * 8);
    }
}

// ---------------------------------------------------------------------------
// fp16 asymmetric 2-pass GEMM: C = Ah[M,K] @ (Bh+Bl)[N,K]^T
// 4 warps, 64x64 per warp.
// MODE: 0 = fp32 out, 1 = half hi out (+lo where n>=lo_start),
//       3 = fused QKV (n<2048 normal hi(+lo for K region), n>=2048 V^T out)
// CAUSAL: 0 none, 1 compacted lower-triangle grid, 2 K-limit (long rows first)
// ---------------------------------------------------------------------------
template<int MODE, int CAUSAL>
__global__ __launch_bounds__(GT, 2)
void hm2(const __half* __restrict__ A,
         const __half* __restrict__ Bh, const __half* __restrict__ Bl,
         float* __restrict__ C32, __half* __restrict__ Chi,
         __half* __restrict__ Clo,
         __half* __restrict__ Vth, __half* __restrict__ Vtl,
         int Nld, int ldA, int ldB, int Kdim, int lo_start,
         size_t sA, size_t sB, size_t sC)
{
    int tileR, tileC;
    if (CAUSAL == 1) {
        // compacted lower-triangle: t -> (r, c), c <= r
        const int t = blockIdx.x;
        int r = (int)((sqrtf(8.0f * t + 1.0f) - 1.0f) * 0.5f);
        while ((r + 1) * (r + 2) / 2 <= t) r++;
        while (r * (r + 1) / 2 > t) r--;
        tileR = r;
        tileC = t - r * (r + 1) / 2;
    } else if (CAUSAL == 2) {
        tileR = gridDim.y - 1 - blockIdx.y;   // long-K rows first
        tileC = blockIdx.x;
    } else {
        tileR = blockIdx.y;
        tileC = blockIdx.x;
    }

    const int row0 = tileR * 128;
    const int col0 = tileC * 128;
    const size_t zb = blockIdx.z;

    extern __shared__ char smem[];
    const uint32_t sb = smem_u32(smem);
    const int tid  = threadIdx.x;
    const int wid  = tid >> 5;
    const int lane = tid & 31;
    const int warp_m = wid >> 1;          // 0..1
    const int warp_n = wid & 1;           // 0..1
    const int gq = lane >> 2;
    const int tq = lane & 3;

    int kEnd = Kdim;
    if (CAUSAL == 2) {
        int lim = (tileR + 1) * 128;
        if (lim < kEnd) kEnd = lim;
    }
    const int nChunks = kEnd / KC;

    const __half* pA  = A  + zb * sA + (size_t)row0 * ldA;
    const __half* pBh = Bh + zb * sB + (size_t)col0 * ldB;
    const __half* pBl = Bl + zb * sB + (size_t)col0 * ldB;

    const int a_r  = lane & 15;
    const int a_kq = (lane >> 4) << 3;
    const int b_r  = (lane & 7) + ((lane >= 16) ? 8 : 0);
    const int b_kq = ((lane >> 3) & 1) << 3;

    // per-warp smem byte offsets (within a stage)
    const uint32_t aoff0 = (warp_m * 64 + a_r) * (LDT * 2) + a_kq * 2;
    const uint32_t boff0 = (warp_n * 64 + b_r) * (LDT * 2) + b_kq * 2;

    float acc[4][8][4];
    #pragma unroll
    for (int i = 0; i < 4; i++)
        #pragma unroll
        for (int j = 0; j < 8; j++)
            #pragma unroll
            for (int q = 0; q < 4; q++) acc[i][j][q] = 0.0f;

    // prologue: prefetch chunk 0 into stage 0
    {
        load_tile_async(sb,              pA,  ldA, tid);
        load_tile_async(sb + TILE_P,     pBh, ldB, tid);
        load_tile_async(sb + 2 * TILE_P, pBl, ldB, tid);
        cpa_commit();
    }

    for (int c = 0; c < nChunks; c++) {
        if (c + 1 < nChunks) {
            const uint32_t stn = sb + ((c + 1) & 1) * STG_B;
            const int k0 = (c + 1) * KC;
            load_tile_async(stn,              pA  + k0, ldA, tid);
            load_tile_async(stn + TILE_P,     pBh + k0, ldB, tid);
            load_tile_async(stn + 2 * TILE_P, pBl + k0, ldB, tid);
            cpa_commit();
            asm volatile("cp.async.wait_group 1;");
        } else {
            asm volatile("cp.async.wait_group 0;");
        }
        __syncthreads();

        const uint32_t st = sb + (c & 1) * STG_B;
        #pragma unroll
        for (int ks = 0; ks < 4; ks++) {
            const uint32_t kb = ks * 32;      // 16 fp16 = 32 bytes
            uint32_t ah[4][4], bh[4][4], bl[4][4];
            #pragma unroll
            for (int mb = 0; mb < 4; mb++)
                ldm_x4(ah[mb], st + aoff0 + mb * 16 * (LDT * 2) + kb);
            #pragma unroll
            for (int nh = 0; nh < 4; nh++) {
                const uint32_t bo = boff0 + nh * 16 * (LDT * 2) + kb;
                ldm_x4(bh[nh], st + TILE_P + bo);
                ldm_x4(bl[nh], st + 2 * TILE_P + bo);
            }
            #pragma unroll
            for (int mb = 0; mb < 4; mb++) {
                #pragma unroll
                for (int nb = 0; nb < 8; nb++) {
                    const int nh = nb >> 1, p = (nb & 1) * 2;
                    mma16816(acc[mb][nb], ah[mb], bh[nh][p], bh[nh][p + 1]);
                    mma16816(acc[mb][nb], ah[mb], bl[nh][p], bl[nh][p + 1]);
                }
            }
        }
        __syncthreads();
    }

    // ---------------- Epilogue ----------------
    const bool vregion = (MODE == 3) && (col0 >= 2048);
    if (!vregion) {
        #pragma unroll
        for (int mb = 0; mb < 4; mb++) {
            const int m = row0 + warp_m * 64 + mb * 16 + gq;
            #pragma unroll
            for (int nb = 0; nb < 8; nb++) {
                const int n = col0 + warp_n * 64 + nb * 8 + tq * 2;
                const float* cc = acc[mb][nb];
                if (MODE == 0) {
                    float* d0 = C32 + zb * sC + (size_t)m * Nld + n;
                    float* d1 = C32 + zb * sC + (size_t)(m + 8) * Nld + n;
                    *reinterpret_cast<float2*>(d0) = make_float2(cc[0], cc[1]);
                    *reinterpret_cast<float2*>(d1) = make_float2(cc[2], cc[3]);
                } else {
                    size_t o0 = zb * sC + (size_t)m * Nld + n;
                    size_t o1 = zb * sC + (size_t)(m + 8) * Nld + n;
                    if (n >= lo_start) {
                        uint32_t hp, lp;
                        split_pack2h(cc[0], cc[1], hp, lp);
                        *reinterpret_cast<uint32_t*>(Chi + o0) = hp;
                        *reinterpret_cast<uint32_t*>(Clo + o0) = lp;
                        split_pack2h(cc[2], cc[3], hp, lp);
                        *reinterpret_cast<uint32_t*>(Chi + o1) = hp;
                        *reinterpret_cast<uint32_t*>(Clo + o1) = lp;
                    } else {
                        *reinterpret_cast<uint32_t*>(Chi + o0) = pack2h(cc[0], cc[1]);
                        *reinterpret_cast<uint32_t*>(Chi + o1) = pack2h(cc[2], cc[3]);
                    }
                }
            }
        }
    } else {
        // V^T region: transpose through smem, write hi+lo (B-side operand)
        float* smt = reinterpret_cast<float*>(smem);   // [128][129]
        __syncthreads();
        #pragma unroll
        for (int mb = 0; mb < 4; mb++) {
            const int m = warp_m * 64 + mb * 16 + gq;
            #pragma unroll
            for (int nb = 0; nb < 8; nb++) {
                const int n = warp_n * 64 + nb * 8 + tq * 2;
                const float* cc = acc[mb][nb];
                smt[m * 129 + n]           = cc[0];
                smt[m * 129 + n + 1]       = cc[1];
                smt[(m + 8) * 129 + n]     = cc[2];
                smt[(m + 8) * 129 + n + 1] = cc[3];
            }
        }
        __syncthreads();
        const int b  = row0 >> 11;
        const int s0 = row0 & (SEQ - 1);
        const int nl = tid;                 // 0..127 (dv within tile)
        const size_t base = (size_t)b * DIM * SEQ +
                            (size_t)(col0 - 2048 + nl) * SEQ + s0;
        #pragma unroll
        for (int u = 0; u < 128; u += 2) {
            uint32_t hp, lp;
            split_pack2h(smt[u * 129 + nl], smt[(u + 1) * 129 + nl], hp, lp);
            *reinterpret_cast<uint32_t*>(Vth + base + u) = hp;
            *reinterpret_cast<uint32_t*>(Vtl + base + u) = lp;
        }
    }
}

// ---------------------------------------------------------------------------
// Preprocess: x fp32 -> fp16 hi only (A-side operand)
// ---------------------------------------------------------------------------
__global__ void split_x(const float* __restrict__ in,
                        __half* __restrict__ xh, size_t n4)
{
    size_t i = (size_t)blockIdx.x * blockDim.x + threadIdx.x;
    if (i >= n4) return;
    float4 v = reinterpret_cast<const float4*>(in)[i];
    uint2 o;
    o.x = pack2h(v.x, v.y);
    o.y = pack2h(v.z, v.w);
    reinterpret_cast<uint2*>(xh)[i] = o;
}

// W [K][N] fp32 -> W^T hi/lo fp16; z selects Wq/Wk/Wv (into concat wqkvt)
// or Wo (into wot).
__global__ void transpose_qkvo(const float* __restrict__ Wq,
                               const float* __restrict__ Wk,
                               const float* __restrict__ Wv,
                               const float* __restrict__ Wo,
                               __half* __restrict__ qkvh,
                               __half* __restrict__ qkvl,
                               __half* __restrict__ woh,
                               __half* __restrict__ wol)
{
    __shared__ float t[32][33];
    const int z = blockIdx.z;
    const float* in = (z == 0) ? Wq : (z == 1) ? Wk : (z == 2) ? Wv : Wo;
    __half* dh = (z < 3) ? qkvh + (size_t)z * DIM * DIM : woh;
    __half* dl = (z < 3) ? qkvl + (size_t)z * DIM * DIM : wol;

    const int bx = blockIdx.x * 32, by = blockIdx.y * 32;
    const int x = threadIdx.x, y = threadIdx.y;   // 32 x 8
    #pragma unroll
    for (int i = 0; i < 32; i += 8)
        t[y + i][x] = in[(size_t)(by + y + i) * DIM + bx + x];
    __syncthreads();
    #pragma unroll
    for (int i = 0; i < 32; i += 8) {
        float v = t[x][y + i];
        __half h = __float2half_rn(v);
        size_t o = (size_t)(bx + y + i) * DIM + by + x;
        dh[o] = h;
        dl[o] = __float2half_rn(v - __half2float(h));
    }
}

// ---------------------------------------------------------------------------
// Causal softmax: fp32 S (lower triangle) -> fp16 P hi; zeros only the
// in-diagonal-tile upper wedge (the only masked entries the PV GEMM reads).
// ---------------------------------------------------------------------------
__global__ void softmax_causal(const float* __restrict__ Sbuf,
                               __half* __restrict__ Ph)
{
    const int i = blockIdx.x;
    const int b = blockIdx.y;
    const size_t off = ((size_t)b * SEQ + i) * SEQ;
    const float* row = Sbuf + off;
    const int n = i + 1;
    const float scale = 0.03125f;   // 1/sqrt(1024)

    __shared__ float red[256];
    const int tid = threadIdx.x;

    float m = -3.402823466e+38f;
    for (int j = tid; j < n; j += 256) m = fmaxf(m, row[j]);
    red[tid] = m;
    __syncthreads();
    #pragma unroll
    for (int s = 128; s > 0; s >>= 1) {
        if (tid < s) red[tid] = fmaxf(red[tid], red[tid + s]);
        __syncthreads();
    }
    const float mx = red[0] * scale;
    __syncthreads();

    float sum = 0.0f;
    for (int j = tid; j < n; j += 256) sum += __expf(row[j] * scale - mx);
    red[tid] = sum;
    __syncthreads();
    #pragma unroll
    for (int s = 128; s > 0; s >>= 1) {
        if (tid < s) red[tid] += red[tid + s];
        __syncthreads();
    }
    const float inv = 1.0f / red[0];

    for (int j = tid; j < n; j += 256)
        Ph[off + j] = __float2half_rn(__expf(row[j] * scale - mx) * inv);

    // zero the rest of the diagonal 128-tile only
    const int tileEnd = ((i >> 7) + 1) << 7;
    for (int j = n + tid; j < tileEnd; j += 256)
        Ph[off + j] = __ushort_as_half((unsigned short)0);
}

// ---------------------------------------------------------------------------
// Launch
// ---------------------------------------------------------------------------
extern "C" void kernel_launch(void* const* d_in, const int* in_sizes, int n_in,
                              void* d_out, int out_size)
{
    const float* x  = (const float*)d_in[0];
    const float* Wq = (const float*)d_in[1];
    const float* Wk = (const float*)d_in[2];
    const float* Wv = (const float*)d_in[3];
    const float* Wo = (const float*)d_in[4];
    float* out = (float*)d_out;

    cudaFuncSetAttribute(hm2<3,0>, cudaFuncAttributeMaxDynamicSharedMemorySize, SMEM_B);
    cudaFuncSetAttribute(hm2<0,1>, cudaFuncAttributeMaxDynamicSharedMemorySize, SMEM_B);
    cudaFuncSetAttribute(hm2<1,2>, cudaFuncAttributeMaxDynamicSharedMemorySize, SMEM_B);
    cudaFuncSetAttribute(hm2<0,0>, cudaFuncAttributeMaxDynamicSharedMemorySize, SMEM_B);

    __half *xh, *qkvh, *qkvl, *woh, *wol, *qkh, *qkl, *vth, *vtl, *ph, *aoh;
    float* S;
    cudaGetSymbolAddress((void**)&xh, g_xh);
    cudaGetSymbolAddress((void**)&qkvh, g_wqkvth);
    cudaGetSymbolAddress((void**)&qkvl, g_wqkvtl);
    cudaGetSymbolAddress((void**)&woh, g_woth);
    cudaGetSymbolAddress((void**)&wol, g_wotl);
    cudaGetSymbolAddress((void**)&qkh, g_qkh);
    cudaGetSymbolAddress((void**)&qkl, g_qkl);
    cudaGetSymbolAddress((void**)&vth, g_vth);
    cudaGetSymbolAddress((void**)&vtl, g_vtl);
    cudaGetSymbolAddress((void**)&ph, g_ph);
    cudaGetSymbolAddress((void**)&aoh, g_aoh);
    cudaGetSymbolAddress((void**)&S, g_S);

    const size_t sQK = (size_t)SEQ * 2 * DIM;   // per-batch Q|K row block
    const size_t sV  = (size_t)DIM * SEQ;
    const size_t sS  = (size_t)SEQ * SEQ;

    // 1) x -> fp16 hi
    split_x<<<(unsigned)((RXD / 4 + 255) / 256), 256>>>(x, xh, RXD / 4);

    // 2) weights: transpose + hi/lo split (Wq|Wk|Wv concat, Wo separate)
    transpose_qkvo<<<dim3(DIM / 32, DIM / 32, 4), dim3(32, 8)>>>(
        Wq, Wk, Wv, Wo, qkvh, qkvl, woh, wol);

    // 3) fused QKV projection: [8192,1024] @ [1024,3072]
    //    n<1024: Q hi; 1024<=n<2048: K hi+lo; n>=2048: V^T hi+lo
    hm2<3,0><<<dim3(3 * DIM / 128, BATCH * SEQ / 128, 1), GT, SMEM_B>>>(
        xh, qkvh, qkvl, nullptr, qkh, qkl, vth, vtl,
        2 * DIM, DIM, DIM, DIM, DIM, 0, 0, 0);

    // 4) scores = Q @ K^T per batch (compacted lower-triangular tile grid)
    hm2<0,1><<<dim3(136, 1, BATCH), GT, SMEM_B>>>(
        qkh, qkh + DIM, qkl + DIM, S, nullptr, nullptr, nullptr, nullptr,
        SEQ, 2 * DIM, 2 * DIM, DIM, 0, sQK, sQK, sS);

    // 5) softmax -> P hi
    softmax_causal<<<dim3(SEQ, BATCH), 256>>>(S, ph);

    // 6) AO = P @ V (B = V^T hi+lo, K-limited, long rows first)
    hm2<1,2><<<dim3(DIM / 128, SEQ / 128, BATCH), GT, SMEM_B>>>(
        ph, vth, vtl, nullptr, aoh, nullptr, nullptr, nullptr,
        DIM, SEQ, SEQ, SEQ, 1 << 30, sS, sV, (size_t)SEQ * DIM);

    // 7) out = AO @ Wo
    hm2<0,0><<<dim3(DIM / 128, BATCH * SEQ / 128, 1), GT, SMEM_B>>>(
        aoh, woh, wol, out, nullptr, nullptr, nullptr, nullptr,
        DIM, DIM, DIM, DIM, 0, 0, 0, 0);
}

// round 8
// speedup vs baseline: 7.1356x; 1.6891x over previous
#include <cuda_runtime.h>
#include <cuda_fp16.h>
#include <cstdint>
#include <cstddef>

// ---------------------------------------------------------------------------
// Problem constants
// ---------------------------------------------------------------------------
#define BATCH 4
#define SEQ   2048
#define DIM   1024

// GEMM tiling: 128x128 CTA tile, 8 warps of 64x32, K chunks of 64 fp16.
#define KC     64
#define LDT    72                       // padded row stride in fp16 (144 B)
#define TILE_P (128 * LDT * 2)          // 18432 B per tile
#define NTILES 2                        // A, B (single-pass fp16)
#define STG_B  (NTILES * TILE_P)        // 36864 B
#define NS     3                        // pipeline stages
#define SMEM_B (NS * STG_B)             // 110592 B -> 2 CTAs/SM
#define GT     256                      // threads per GEMM CTA (8 warps)

// ---------------------------------------------------------------------------
// PTX helpers (base sm_103 ISA: cp.async, ldmatrix, mma.sync)
// ---------------------------------------------------------------------------
__device__ __forceinline__ uint32_t smem_u32(const void* p) {
    uint32_t a;
    asm("{ .reg .u64 t; cvta.to.shared.u64 t, %1; cvt.u32.u64 %0, t; }"
        : "=r"(a) : "l"(p));
    return a;
}
__device__ __forceinline__ void cpa16(uint32_t dst, const void* src) {
    asm volatile("cp.async.cg.shared.global [%0], [%1], 16;"
                 :: "r"(dst), "l"(src));
}
__device__ __forceinline__ void cpa_commit() {
    asm volatile("cp.async.commit_group;");
}
__device__ __forceinline__ void ldm_x4(uint32_t* r, uint32_t addr) {
    asm volatile("ldmatrix.sync.aligned.m8n8.x4.shared.b16 {%0,%1,%2,%3}, [%4];"
                 : "=r"(r[0]), "=r"(r[1]), "=r"(r[2]), "=r"(r[3]) : "r"(addr));
}
__device__ __forceinline__ void mma16816(float* d, const uint32_t* a,
                                         uint32_t b0, uint32_t b1) {
    asm volatile(
        "mma.sync.aligned.m16n8k16.row.col.f32.f16.f16.f32 "
        "{%0,%1,%2,%3}, {%4,%5,%6,%7}, {%8,%9}, {%0,%1,%2,%3};"
        : "+f"(d[0]), "+f"(d[1]), "+f"(d[2]), "+f"(d[3])
        : "r"(a[0]), "r"(a[1]), "r"(a[2]), "r"(a[3]), "r"(b0), "r"(b1));
}
__device__ __forceinline__ uint32_t pack2h(float a, float b) {
    __half ha = __float2half_rn(a), hb = __float2half_rn(b);
    return (uint32_t)__half_as_ushort(ha) | ((uint32_t)__half_as_ushort(hb) << 16);
}

// ---------------------------------------------------------------------------
// Device scratch
// ---------------------------------------------------------------------------
#define RXD ((size_t)BATCH * SEQ * DIM)
#define RSS ((size_t)BATCH * SEQ * SEQ)
__device__ __half g_xh[RXD];                             // x fp16
__device__ __half g_wqkvth[3 * DIM * DIM];               // W_{q|k|v}^T fp16
__device__ __half g_woth[DIM * DIM];                     // Wo^T fp16
__device__ __half g_qkh[(size_t)BATCH * SEQ * 2 * DIM];  // Q|K fp16 [8192][2048]
__device__ __half g_vth[RXD];                            // V^T fp16 [B][DV][SEQ]
__device__ float  g_S[RSS];
__device__ __half g_ph[RSS];                             // P fp16
__device__ __half g_aoh[RXD];                            // AO fp16

// ---------------------------------------------------------------------------
// Async tile load: 128 rows x 64 fp16 (K-major) -> padded smem (stride LDT)
// ---------------------------------------------------------------------------
__device__ __forceinline__ void load_tile_async(uint32_t base,
                                                const __half* __restrict__ gp,
                                                int ld, int tid) {
    #pragma unroll
    for (int i = 0; i < 4; i++) {
        int idx = i * GT + tid;           // 0..1023
        int row = idx >> 3;
        int c16 = idx & 7;
        cpa16(base + row * (LDT * 2) + c16 * 16,
              gp + (size_t)row * ld + c16 * 8);
    }
}

// ---------------------------------------------------------------------------
// Single-pass fp16 GEMM: C[M,N] = A[M,K] @ B[N,K]^T (both K-major)
// 8 warps of 64x32.
// MODE: 0 = fp32 out, 1 = fp16 out,
//       3 = fused QKV (n<2048 -> Q|K fp16; n>=2048 -> V^T fp16)
// CAUSAL: 0 none, 1 compacted lower-triangle grid, 2 K-limit (long rows first)
// ---------------------------------------------------------------------------
template<int MODE, int CAUSAL>
__global__ __launch_bounds__(GT, 2)
void hm1(const __half* __restrict__ A, const __half* __restrict__ B,
         float* __restrict__ C32, __half* __restrict__ Chi,
         __half* __restrict__ Vth,
         int Nld, int ldA, int ldB, int Kdim,
         size_t sA, size_t sB, size_t sC)
{
    int tileR, tileC;
    if (CAUSAL == 1) {
        const int t = blockIdx.x;
        int r = (int)((sqrtf(8.0f * t + 1.0f) - 1.0f) * 0.5f);
        while ((r + 1) * (r + 2) / 2 <= t) r++;
        while (r * (r + 1) / 2 > t) r--;
        tileR = r;
        tileC = t - r * (r + 1) / 2;
    } else if (CAUSAL == 2) {
        tileR = gridDim.y - 1 - blockIdx.y;   // long-K rows first
        tileC = blockIdx.x;
    } else {
        tileR = blockIdx.y;
        tileC = blockIdx.x;
    }

    const int row0 = tileR * 128;
    const int col0 = tileC * 128;
    const size_t zb = blockIdx.z;

    extern __shared__ char smem[];
    const uint32_t sb = smem_u32(smem);
    const int tid  = threadIdx.x;
    const int wid  = tid >> 5;
    const int lane = tid & 31;
    const int warp_m = wid >> 2;          // 0..1
    const int warp_n = wid & 3;           // 0..3
    const int gq = lane >> 2;
    const int tq = lane & 3;

    int kEnd = Kdim;
    if (CAUSAL == 2) {
        int lim = (tileR + 1) * 128;
        if (lim < kEnd) kEnd = lim;
    }
    const int nChunks = kEnd / KC;

    const __half* pA = A + zb * sA + (size_t)row0 * ldA;
    const __half* pB = B + zb * sB + (size_t)col0 * ldB;

    const int a_r  = lane & 15;
    const int a_kq = (lane >> 4) << 3;
    const int b_r  = (lane & 7) + ((lane >= 16) ? 8 : 0);
    const int b_kq = ((lane >> 3) & 1) << 3;

    const uint32_t aoff0 = (warp_m * 64 + a_r) * (LDT * 2) + a_kq * 2;
    const uint32_t boff0 = (warp_n * 32 + b_r) * (LDT * 2) + b_kq * 2;

    float acc[4][4][4];
    #pragma unroll
    for (int i = 0; i < 4; i++)
        #pragma unroll
        for (int j = 0; j < 4; j++)
            #pragma unroll
            for (int q = 0; q < 4; q++) acc[i][j][q] = 0.0f;

    // prologue: prefetch NS-1 chunks (always commit so wait counts line up)
    #pragma unroll
    for (int s = 0; s < NS - 1; s++) {
        if (s < nChunks) {
            const uint32_t st = sb + s * STG_B;
            const int k0 = s * KC;
            load_tile_async(st,          pA + k0, ldA, tid);
            load_tile_async(st + TILE_P, pB + k0, ldB, tid);
        }
        cpa_commit();
    }

    for (int c = 0; c < nChunks; c++) {
        asm volatile("cp.async.wait_group %0;" :: "n"(NS - 2));
        __syncthreads();

        const uint32_t st = sb + (c % NS) * STG_B;
        #pragma unroll
        for (int ks = 0; ks < 4; ks++) {
            const uint32_t kb = ks * 32;      // 16 fp16 = 32 bytes
            uint32_t ah[4][4], bh[2][4];
            #pragma unroll
            for (int mb = 0; mb < 4; mb++)
                ldm_x4(ah[mb], st + aoff0 + mb * 16 * (LDT * 2) + kb);
            #pragma unroll
            for (int nh = 0; nh < 2; nh++)
                ldm_x4(bh[nh], st + TILE_P + boff0 + nh * 16 * (LDT * 2) + kb);
            #pragma unroll
            for (int mb = 0; mb < 4; mb++) {
                #pragma unroll
                for (int nb = 0; nb < 4; nb++) {
                    const int nh = nb >> 1, p = (nb & 1) * 2;
                    mma16816(acc[mb][nb], ah[mb], bh[nh][p], bh[nh][p + 1]);
                }
            }
        }
        __syncthreads();

        // prefetch chunk c + NS - 1 into the stage just freed
        const int cn = c + NS - 1;
        if (cn < nChunks) {
            const uint32_t stn = sb + (cn % NS) * STG_B;
            const int k0 = cn * KC;
            load_tile_async(stn,          pA + k0, ldA, tid);
            load_tile_async(stn + TILE_P, pB + k0, ldB, tid);
        }
        cpa_commit();
    }

    // ---------------- Epilogue ----------------
    const bool vregion = (MODE == 3) && (col0 >= 2048);
    if (!vregion) {
        #pragma unroll
        for (int mb = 0; mb < 4; mb++) {
            const int m = row0 + warp_m * 64 + mb * 16 + gq;
            #pragma unroll
            for (int nb = 0; nb < 4; nb++) {
                const int n = col0 + warp_n * 32 + nb * 8 + tq * 2;
                const float* cc = acc[mb][nb];
                if (MODE == 0) {
                    float* d0 = C32 + zb * sC + (size_t)m * Nld + n;
                    float* d1 = C32 + zb * sC + (size_t)(m + 8) * Nld + n;
                    *reinterpret_cast<float2*>(d0) = make_float2(cc[0], cc[1]);
                    *reinterpret_cast<float2*>(d1) = make_float2(cc[2], cc[3]);
                } else {
                    size_t o0 = zb * sC + (size_t)m * Nld + n;
                    size_t o1 = zb * sC + (size_t)(m + 8) * Nld + n;
                    *reinterpret_cast<uint32_t*>(Chi + o0) = pack2h(cc[0], cc[1]);
                    *reinterpret_cast<uint32_t*>(Chi + o1) = pack2h(cc[2], cc[3]);
                }
            }
        }
    } else {
        // V^T region: transpose through smem, write fp16
        float* smt = reinterpret_cast<float*>(smem);   // [128][129]
        __syncthreads();
        #pragma unroll
        for (int mb = 0; mb < 4; mb++) {
            const int m = warp_m * 64 + mb * 16 + gq;
            #pragma unroll
            for (int nb = 0; nb < 4; nb++) {
                const int n = warp_n * 32 + nb * 8 + tq * 2;
                const float* cc = acc[mb][nb];
                smt[m * 129 + n]           = cc[0];
                smt[m * 129 + n + 1]       = cc[1];
                smt[(m + 8) * 129 + n]     = cc[2];
                smt[(m + 8) * 129 + n + 1] = cc[3];
            }
        }
        __syncthreads();
        const int b  = row0 >> 11;
        const int s0 = row0 & (SEQ - 1);
        const int nl = tid >> 1;            // 0..127 (dv within tile)
        const int sh = (tid & 1) * 64;      // s half
        const size_t base = (size_t)b * DIM * SEQ +
                            (size_t)(col0 - 2048 + nl) * SEQ + s0 + sh;
        #pragma unroll
        for (int u = 0; u < 64; u += 2) {
            *reinterpret_cast<uint32_t*>(Vth + base + u) =
                pack2h(smt[(sh + u) * 129 + nl], smt[(sh + u + 1) * 129 + nl]);
        }
    }
}

// ---------------------------------------------------------------------------
// Preprocess: x fp32 -> fp16
// ---------------------------------------------------------------------------
__global__ void split_x(const float* __restrict__ in,
                        __half* __restrict__ xh, size_t n4)
{
    size_t i = (size_t)blockIdx.x * blockDim.x + threadIdx.x;
    if (i >= n4) return;
    float4 v = reinterpret_cast<const float4*>(in)[i];
    uint2 o;
    o.x = pack2h(v.x, v.y);
    o.y = pack2h(v.z, v.w);
    reinterpret_cast<uint2*>(xh)[i] = o;
}

// W [K][N] fp32 -> W^T fp16; z selects Wq/Wk/Wv (into concat) or Wo.
__global__ void transpose_qkvo(const float* __restrict__ Wq,
                               const float* __restrict__ Wk,
                               const float* __restrict__ Wv,
                               const float* __restrict__ Wo,
                               __half* __restrict__ qkvh,
                               __half* __restrict__ woh)
{
    __shared__ float t[32][33];
    const int z = blockIdx.z;
    const float* in = (z == 0) ? Wq : (z == 1) ? Wk : (z == 2) ? Wv : Wo;
    __half* dh = (z < 3) ? qkvh + (size_t)z * DIM * DIM : woh;

    const int bx = blockIdx.x * 32, by = blockIdx.y * 32;
    const int x = threadIdx.x, y = threadIdx.y;   // 32 x 8
    #pragma unroll
    for (int i = 0; i < 32; i += 8)
        t[y + i][x] = in[(size_t)(by + y + i) * DIM + bx + x];
    __syncthreads();
    #pragma unroll
    for (int i = 0; i < 32; i += 8)
        dh[(size_t)(bx + y + i) * DIM + by + x] = __float2half_rn(t[x][y + i]);
}

// ---------------------------------------------------------------------------
// Causal softmax: fp32 S (lower triangle) -> fp16 P; zeros only the
// in-diagonal-tile upper wedge (the only masked entries the PV GEMM reads).
// ---------------------------------------------------------------------------
__global__ void softmax_causal(const float* __restrict__ Sbuf,
                               __half* __restrict__ Ph)
{
    const int i = blockIdx.x;
    const int b = blockIdx.y;
    const size_t off = ((size_t)b * SEQ + i) * SEQ;
    const float* row = Sbuf + off;
    const int n = i + 1;
    const float scale = 0.03125f;   // 1/sqrt(1024)

    __shared__ float red[256];
    const int tid = threadIdx.x;

    float m = -3.402823466e+38f;
    for (int j = tid; j < n; j += 256) m = fmaxf(m, row[j]);
    red[tid] = m;
    __syncthreads();
    #pragma unroll
    for (int s = 128; s > 0; s >>= 1) {
        if (tid < s) red[tid] = fmaxf(red[tid], red[tid + s]);
        __syncthreads();
    }
    const float mx = red[0] * scale;
    __syncthreads();

    float sum = 0.0f;
    for (int j = tid; j < n; j += 256) sum += __expf(row[j] * scale - mx);
    red[tid] = sum;
    __syncthreads();
    #pragma unroll
    for (int s = 128; s > 0; s >>= 1) {
        if (tid < s) red[tid] += red[tid + s];
        __syncthreads();
    }
    const float inv = 1.0f / red[0];

    for (int j = tid; j < n; j += 256)
        Ph[off + j] = __float2half_rn(__expf(row[j] * scale - mx) * inv);

    // zero the rest of the diagonal 128-tile only
    const int tileEnd = ((i >> 7) + 1) << 7;
    for (int j = n + tid; j < tileEnd; j += 256)
        Ph[off + j] = __ushort_as_half((unsigned short)0);
}

// ---------------------------------------------------------------------------
// Launch
// ---------------------------------------------------------------------------
extern "C" void kernel_launch(void* const* d_in, const int* in_sizes, int n_in,
                              void* d_out, int out_size)
{
    const float* x  = (const float*)d_in[0];
    const float* Wq = (const float*)d_in[1];
    const float* Wk = (const float*)d_in[2];
    const float* Wv = (const float*)d_in[3];
    const float* Wo = (const float*)d_in[4];
    float* out = (float*)d_out;

    cudaFuncSetAttribute(hm1<3,0>, cudaFuncAttributeMaxDynamicSharedMemorySize, SMEM_B);
    cudaFuncSetAttribute(hm1<0,1>, cudaFuncAttributeMaxDynamicSharedMemorySize, SMEM_B);
    cudaFuncSetAttribute(hm1<1,2>, cudaFuncAttributeMaxDynamicSharedMemorySize, SMEM_B);
    cudaFuncSetAttribute(hm1<0,0>, cudaFuncAttributeMaxDynamicSharedMemorySize, SMEM_B);

    __half *xh, *qkvh, *woh, *qkh, *vth, *ph, *aoh;
    float* S;
    cudaGetSymbolAddress((void**)&xh, g_xh);
    cudaGetSymbolAddress((void**)&qkvh, g_wqkvth);
    cudaGetSymbolAddress((void**)&woh, g_woth);
    cudaGetSymbolAddress((void**)&qkh, g_qkh);
    cudaGetSymbolAddress((void**)&vth, g_vth);
    cudaGetSymbolAddress((void**)&ph, g_ph);
    cudaGetSymbolAddress((void**)&aoh, g_aoh);
    cudaGetSymbolAddress((void**)&S, g_S);

    const size_t sQK = (size_t)SEQ * 2 * DIM;   // per-batch Q|K row block
    const size_t sV  = (size_t)DIM * SEQ;
    const size_t sS  = (size_t)SEQ * SEQ;

    // 1) x -> fp16
    split_x<<<(unsigned)((RXD / 4 + 255) / 256), 256>>>(x, xh, RXD / 4);

    // 2) weights: transpose to fp16 (Wq|Wk|Wv concat, Wo separate)
    transpose_qkvo<<<dim3(DIM / 32, DIM / 32, 4), dim3(32, 8)>>>(
        Wq, Wk, Wv, Wo, qkvh, woh);

    // 3) fused QKV projection: [8192,1024] @ [1024,3072]
    //    n<2048: Q|K fp16; n>=2048: V^T fp16
    hm1<3,0><<<dim3(3 * DIM / 128, BATCH * SEQ / 128, 1), GT, SMEM_B>>>(
        xh, qkvh, nullptr, qkh, vth,
        2 * DIM, DIM, DIM, DIM, 0, 0, 0);

    // 4) scores = Q @ K^T per batch (compacted lower-triangular tile grid)
    hm1<0,1><<<dim3(136, 1, BATCH), GT, SMEM_B>>>(
        qkh, qkh + DIM, S, nullptr, nullptr,
        SEQ, 2 * DIM, 2 * DIM, DIM, sQK, sQK, sS);

    // 5) softmax -> P fp16
    softmax_causal<<<dim3(SEQ, BATCH), 256>>>(S, ph);

    // 6) AO = P @ V (B = V^T, K-limited, long rows first)
    hm1<1,2><<<dim3(DIM / 128, SEQ / 128, BATCH), GT, SMEM_B>>>(
        ph, vth, nullptr, aoh, nullptr,
        DIM, SEQ, SEQ, SEQ, sS, sV, (size_t)SEQ * DIM);

    // 7) out = AO @ Wo
    hm1<0,0><<<dim3(DIM / 128, BATCH * SEQ / 128, 1), GT, SMEM_B>>>(
        aoh, woh, out, nullptr, nullptr,
        DIM, DIM, DIM, DIM, 0, 0, 0);
}

// round 9
// speedup vs baseline: 7.7343x; 1.0839x over previous
#include <cuda_runtime.h>
#include <cuda_fp16.h>
#include <cstdint>
#include <cstddef>

// ---------------------------------------------------------------------------
// Problem constants
// ---------------------------------------------------------------------------
#define BATCH 4
#define SEQ   2048
#define DIM   1024

// GEMM tiling: 128x128 CTA tile, 4 warps of 64x64, K chunks of 64 fp16.
#define KC     64
#define LDT    72                       // padded row stride in fp16 (144 B)
#define TILE_P (128 * LDT * 2)          // 18432 B per tile
#define NTILES 2                        // A, B (single-pass fp16)
#define STG_B  (NTILES * TILE_P)        // 36864 B
#define NS     3                        // pipeline stages
#define SMEM_B (NS * STG_B)             // 110592 B -> 2 CTAs/SM
#define GT     128                      // threads per GEMM CTA (4 warps)

// ---------------------------------------------------------------------------
// PTX helpers (base sm_103 ISA: cp.async, ldmatrix, mma.sync)
// ---------------------------------------------------------------------------
__device__ __forceinline__ uint32_t smem_u32(const void* p) {
    uint32_t a;
    asm("{ .reg .u64 t; cvta.to.shared.u64 t, %1; cvt.u32.u64 %0, t; }"
        : "=r"(a) : "l"(p));
    return a;
}
__device__ __forceinline__ void cpa16(uint32_t dst, const void* src) {
    asm volatile("cp.async.cg.shared.global [%0], [%1], 16;"
                 :: "r"(dst), "l"(src));
}
__device__ __forceinline__ void cpa_commit() {
    asm volatile("cp.async.commit_group;");
}
__device__ __forceinline__ void ldm_x4(uint32_t* r, uint32_t addr) {
    asm volatile("ldmatrix.sync.aligned.m8n8.x4.shared.b16 {%0,%1,%2,%3}, [%4];"
                 : "=r"(r[0]), "=r"(r[1]), "=r"(r[2]), "=r"(r[3]) : "r"(addr));
}
__device__ __forceinline__ void mma16816(float* d, const uint32_t* a,
                                         uint32_t b0, uint32_t b1) {
    asm volatile(
        "mma.sync.aligned.m16n8k16.row.col.f32.f16.f16.f32 "
        "{%0,%1,%2,%3}, {%4,%5,%6,%7}, {%8,%9}, {%0,%1,%2,%3};"
        : "+f"(d[0]), "+f"(d[1]), "+f"(d[2]), "+f"(d[3])
        : "r"(a[0]), "r"(a[1]), "r"(a[2]), "r"(a[3]), "r"(b0), "r"(b1));
}
__device__ __forceinline__ uint32_t pack2h(float a, float b) {
    __half ha = __float2half_rn(a), hb = __float2half_rn(b);
    return (uint32_t)__half_as_ushort(ha) | ((uint32_t)__half_as_ushort(hb) << 16);
}

// ---------------------------------------------------------------------------
// Device scratch
// ---------------------------------------------------------------------------
#define RXD ((size_t)BATCH * SEQ * DIM)
#define RSS ((size_t)BATCH * SEQ * SEQ)
__device__ __half g_xh[RXD];                             // x fp16
__device__ __half g_wqkvth[3 * DIM * DIM];               // W_{q|k|v}^T fp16
__device__ __half g_woth[DIM * DIM];                     // Wo^T fp16
__device__ __half g_qkh[(size_t)BATCH * SEQ * 2 * DIM];  // Q|K fp16 [8192][2048]
__device__ __half g_vth[RXD];                            // V^T fp16 [B][DV][SEQ]
__device__ float  g_S[RSS];
__device__ __half g_ph[RSS];                             // P fp16
__device__ __half g_aoh[RXD];                            // AO fp16

// ---------------------------------------------------------------------------
// Async tile load: 128 rows x 64 fp16 (K-major) -> padded smem (stride LDT)
// ---------------------------------------------------------------------------
__device__ __forceinline__ void load_tile_async(uint32_t base,
                                                const __half* __restrict__ gp,
                                                int ld, int tid) {
    #pragma unroll
    for (int i = 0; i < 8; i++) {
        int idx = i * GT + tid;           // 0..1023
        int row = idx >> 3;
        int c16 = idx & 7;
        cpa16(base + row * (LDT * 2) + c16 * 16,
              gp + (size_t)row * ld + c16 * 8);
    }
}

// ---------------------------------------------------------------------------
// Single-pass fp16 GEMM: C[M,N] = A[M,K] @ B[N,K]^T (both K-major)
// 4 warps of 64x64, explicit k-step operand double buffering,
// ONE barrier per chunk (NS=3 makes the post-compute barrier redundant).
// MODE: 0 = fp32 out, 1 = fp16 out,
//       3 = fused QKV (n<2048 -> Q|K fp16; n>=2048 -> V^T fp16)
// CAUSAL: 0 none, 1 compacted lower-triangle grid, 2 K-limit (long rows first)
// ---------------------------------------------------------------------------
template<int MODE, int CAUSAL>
__global__ __launch_bounds__(GT, 2)
void hm1(const __half* __restrict__ A, const __half* __restrict__ B,
         float* __restrict__ C32, __half* __restrict__ Chi,
         __half* __restrict__ Vth,
         int Nld, int ldA, int ldB, int Kdim,
         size_t sA, size_t sB, size_t sC)
{
    int tileR, tileC;
    if (CAUSAL == 1) {
        const int t = blockIdx.x;
        int r = (int)((sqrtf(8.0f * t + 1.0f) - 1.0f) * 0.5f);
        while ((r + 1) * (r + 2) / 2 <= t) r++;
        while (r * (r + 1) / 2 > t) r--;
        tileR = r;
        tileC = t - r * (r + 1) / 2;
    } else if (CAUSAL == 2) {
        tileR = gridDim.y - 1 - blockIdx.y;   // long-K rows first
        tileC = blockIdx.x;
    } else {
        tileR = blockIdx.y;
        tileC = blockIdx.x;
    }

    const int row0 = tileR * 128;
    const int col0 = tileC * 128;
    const size_t zb = blockIdx.z;

    extern __shared__ char smem[];
    const uint32_t sb = smem_u32(smem);
    const int tid  = threadIdx.x;
    const int wid  = tid >> 5;
    const int lane = tid & 31;
    const int warp_m = wid >> 1;          // 0..1
    const int warp_n = wid & 1;           // 0..1
    const int gq = lane >> 2;
    const int tq = lane & 3;

    int kEnd = Kdim;
    if (CAUSAL == 2) {
        int lim = (tileR + 1) * 128;
        if (lim < kEnd) kEnd = lim;
    }
    const int nChunks = kEnd / KC;

    const __half* pA = A + zb * sA + (size_t)row0 * ldA;
    const __half* pB = B + zb * sB + (size_t)col0 * ldB;

    const int a_r  = lane & 15;
    const int a_kq = (lane >> 4) << 3;
    const int b_r  = (lane & 7) + ((lane >= 16) ? 8 : 0);
    const int b_kq = ((lane >> 3) & 1) << 3;

    const uint32_t aoff0 = (warp_m * 64 + a_r) * (LDT * 2) + a_kq * 2;
    const uint32_t boff0 = (warp_n * 64 + b_r) * (LDT * 2) + b_kq * 2;

    float acc[4][8][4];
    #pragma unroll
    for (int i = 0; i < 4; i++)
        #pragma unroll
        for (int j = 0; j < 8; j++)
            #pragma unroll
            for (int q = 0; q < 4; q++) acc[i][j][q] = 0.0f;

    // prologue: prefetch NS-1 chunks (always commit so wait counts line up)
    #pragma unroll
    for (int s = 0; s < NS - 1; s++) {
        if (s < nChunks) {
            const uint32_t st = sb + s * STG_B;
            const int k0 = s * KC;
            load_tile_async(st,          pA + k0, ldA, tid);
            load_tile_async(st + TILE_P, pB + k0, ldB, tid);
        }
        cpa_commit();
    }

    uint32_t ah[2][4][4], bh[2][4][4];    // double-buffered k-step operands

    for (int c = 0; c < nChunks; c++) {
        asm volatile("cp.async.wait_group %0;" :: "n"(NS - 2));
        __syncthreads();

        const uint32_t st = sb + (c % NS) * STG_B;

        // k-step 0 operand loads
        #pragma unroll
        for (int mb = 0; mb < 4; mb++)
            ldm_x4(ah[0][mb], st + aoff0 + mb * 16 * (LDT * 2));
        #pragma unroll
        for (int nh = 0; nh < 4; nh++)
            ldm_x4(bh[0][nh], st + TILE_P + boff0 + nh * 16 * (LDT * 2));

        #pragma unroll
        for (int ks = 0; ks < 4; ks++) {
            const int cur = ks & 1;
            // prefetch next k-step operands into the other buffer
            if (ks < 3) {
                const uint32_t kb = (ks + 1) * 32;
                #pragma unroll
                for (int mb = 0; mb < 4; mb++)
                    ldm_x4(ah[cur ^ 1][mb],
                           st + aoff0 + mb * 16 * (LDT * 2) + kb);
                #pragma unroll
                for (int nh = 0; nh < 4; nh++)
                    ldm_x4(bh[cur ^ 1][nh],
                           st + TILE_P + boff0 + nh * 16 * (LDT * 2) + kb);
            }
            #pragma unroll
            for (int mb = 0; mb < 4; mb++) {
                #pragma unroll
                for (int nb = 0; nb < 8; nb++) {
                    const int nh = nb >> 1, p = (nb & 1) * 2;
                    mma16816(acc[mb][nb], ah[cur][mb],
                             bh[cur][nh][p], bh[cur][nh][p + 1]);
                }
            }
        }

        // prefetch chunk c + NS - 1 into the stage just freed.
        // NO barrier needed: stage (c+NS-1)%NS was last READ in chunk c-1,
        // and every warp passed the top-of-loop barrier of chunk c (which
        // postdates its chunk c-1 reads).
        const int cn = c + NS - 1;
        if (cn < nChunks) {
            const uint32_t stn = sb + (cn % NS) * STG_B;
            const int k0 = cn * KC;
            load_tile_async(stn,          pA + k0, ldA, tid);
            load_tile_async(stn + TILE_P, pB + k0, ldB, tid);
        }
        cpa_commit();
    }

    // ---------------- Epilogue ----------------
    const bool vregion = (MODE == 3) && (col0 >= 2048);
    if (!vregion) {
        #pragma unroll
        for (int mb = 0; mb < 4; mb++) {
            const int m = row0 + warp_m * 64 + mb * 16 + gq;
            #pragma unroll
            for (int nb = 0; nb < 8; nb++) {
                const int n = col0 + warp_n * 64 + nb * 8 + tq * 2;
                const float* cc = acc[mb][nb];
                if (MODE == 0) {
                    float* d0 = C32 + zb * sC + (size_t)m * Nld + n;
                    float* d1 = C32 + zb * sC + (size_t)(m + 8) * Nld + n;
                    *reinterpret_cast<float2*>(d0) = make_float2(cc[0], cc[1]);
                    *reinterpret_cast<float2*>(d1) = make_float2(cc[2], cc[3]);
                } else {
                    size_t o0 = zb * sC + (size_t)m * Nld + n;
                    size_t o1 = zb * sC + (size_t)(m + 8) * Nld + n;
                    *reinterpret_cast<uint32_t*>(Chi + o0) = pack2h(cc[0], cc[1]);
                    *reinterpret_cast<uint32_t*>(Chi + o1) = pack2h(cc[2], cc[3]);
                }
            }
        }
    } else {
        // V^T region: transpose through smem, write fp16
        float* smt = reinterpret_cast<float*>(smem);   // [128][129]
        __syncthreads();
        #pragma unroll
        for (int mb = 0; mb < 4; mb++) {
            const int m = warp_m * 64 + mb * 16 + gq;
            #pragma unroll
            for (int nb = 0; nb < 8; nb++) {
                const int n = warp_n * 64 + nb * 8 + tq * 2;
                const float* cc = acc[mb][nb];
                smt[m * 129 + n]           = cc[0];
                smt[m * 129 + n + 1]       = cc[1];
                smt[(m + 8) * 129 + n]     = cc[2];
                smt[(m + 8) * 129 + n + 1] = cc[3];
            }
        }
        __syncthreads();
        const int b  = row0 >> 11;
        const int s0 = row0 & (SEQ - 1);
        const int nl = tid;                 // 0..127 (dv within tile)
        const size_t base = (size_t)b * DIM * SEQ +
                            (size_t)(col0 - 2048 + nl) * SEQ + s0;
        #pragma unroll
        for (int u = 0; u < 128; u += 2) {
            *reinterpret_cast<uint32_t*>(Vth + base + u) =
                pack2h(smt[u * 129 + nl], smt[(u + 1) * 129 + nl]);
        }
    }
}

// ---------------------------------------------------------------------------
// Preprocess: x fp32 -> fp16
// ---------------------------------------------------------------------------
__global__ void split_x(const float* __restrict__ in,
                        __half* __restrict__ xh, size_t n4)
{
    size_t i = (size_t)blockIdx.x * blockDim.x + threadIdx.x;
    if (i >= n4) return;
    float4 v = reinterpret_cast<const float4*>(in)[i];
    uint2 o;
    o.x = pack2h(v.x, v.y);
    o.y = pack2h(v.z, v.w);
    reinterpret_cast<uint2*>(xh)[i] = o;
}

// W [K][N] fp32 -> W^T fp16; z selects Wq/Wk/Wv (into concat) or Wo.
__global__ void transpose_qkvo(const float* __restrict__ Wq,
                               const float* __restrict__ Wk,
                               const float* __restrict__ Wv,
                               const float* __restrict__ Wo,
                               __half* __restrict__ qkvh,
                               __half* __restrict__ woh)
{
    __shared__ float t[32][33];
    const int z = blockIdx.z;
    const float* in = (z == 0) ? Wq : (z == 1) ? Wk : (z == 2) ? Wv : Wo;
    __half* dh = (z < 3) ? qkvh + (size_t)z * DIM * DIM : woh;

    const int bx = blockIdx.x * 32, by = blockIdx.y * 32;
    const int x = threadIdx.x, y = threadIdx.y;   // 32 x 8
    #pragma unroll
    for (int i = 0; i < 32; i += 8)
        t[y + i][x] = in[(size_t)(by + y + i) * DIM + bx + x];
    __syncthreads();
    #pragma unroll
    for (int i = 0; i < 32; i += 8)
        dh[(size_t)(bx + y + i) * DIM + by + x] = __float2half_rn(t[x][y + i]);
}

// ---------------------------------------------------------------------------
// Causal softmax: fp32 S (lower triangle) -> fp16 P; zeros only the
// in-diagonal-tile upper wedge (the only masked entries the PV GEMM reads).
// ---------------------------------------------------------------------------
__global__ void softmax_causal(const float* __restrict__ Sbuf,
                               __half* __restrict__ Ph)
{
    const int i = blockIdx.x;
    const int b = blockIdx.y;
    const size_t off = ((size_t)b * SEQ + i) * SEQ;
    const float* row = Sbuf + off;
    const int n = i + 1;
    const float scale = 0.03125f;   // 1/sqrt(1024)

    __shared__ float red[256];
    const int tid = threadIdx.x;

    float m = -3.402823466e+38f;
    for (int j = tid; j < n; j += 256) m = fmaxf(m, row[j]);
    red[tid] = m;
    __syncthreads();
    #pragma unroll
    for (int s = 128; s > 0; s >>= 1) {
        if (tid < s) red[tid] = fmaxf(red[tid], red[tid + s]);
        __syncthreads();
    }
    const float mx = red[0] * scale;
    __syncthreads();

    float sum = 0.0f;
    for (int j = tid; j < n; j += 256) sum += __expf(row[j] * scale - mx);
    red[tid] = sum;
    __syncthreads();
    #pragma unroll
    for (int s = 128; s > 0; s >>= 1) {
        if (tid < s) red[tid] += red[tid + s];
        __syncthreads();
    }
    const float inv = 1.0f / red[0];

    for (int j = tid; j < n; j += 256)
        Ph[off + j] = __float2half_rn(__expf(row[j] * scale - mx) * inv);

    // zero the rest of the diagonal 128-tile only
    const int tileEnd = ((i >> 7) + 1) << 7;
    for (int j = n + tid; j < tileEnd; j += 256)
        Ph[off + j] = __ushort_as_half((unsigned short)0);
}

// ---------------------------------------------------------------------------
// Launch
// ---------------------------------------------------------------------------
extern "C" void kernel_launch(void* const* d_in, const int* in_sizes, int n_in,
                              void* d_out, int out_size)
{
    const float* x  = (const float*)d_in[0];
    const float* Wq = (const float*)d_in[1];
    const float* Wk = (const float*)d_in[2];
    const float* Wv = (const float*)d_in[3];
    const float* Wo = (const float*)d_in[4];
    float* out = (float*)d_out;

    cudaFuncSetAttribute(hm1<3,0>, cudaFuncAttributeMaxDynamicSharedMemorySize, SMEM_B);
    cudaFuncSetAttribute(hm1<0,1>, cudaFuncAttributeMaxDynamicSharedMemorySize, SMEM_B);
    cudaFuncSetAttribute(hm1<1,2>, cudaFuncAttributeMaxDynamicSharedMemorySize, SMEM_B);
    cudaFuncSetAttribute(hm1<0,0>, cudaFuncAttributeMaxDynamicSharedMemorySize, SMEM_B);

    __half *xh, *qkvh, *woh, *qkh, *vth, *ph, *aoh;
    float* S;
    cudaGetSymbolAddress((void**)&xh, g_xh);
    cudaGetSymbolAddress((void**)&qkvh, g_wqkvth);
    cudaGetSymbolAddress((void**)&woh, g_woth);
    cudaGetSymbolAddress((void**)&qkh, g_qkh);
    cudaGetSymbolAddress((void**)&vth, g_vth);
    cudaGetSymbolAddress((void**)&ph, g_ph);
    cudaGetSymbolAddress((void**)&aoh, g_aoh);
    cudaGetSymbolAddress((void**)&S, g_S);

    const size_t sQK = (size_t)SEQ * 2 * DIM;   // per-batch Q|K row block
    const size_t sV  = (size_t)DIM * SEQ;
    const size_t sS  = (size_t)SEQ * SEQ;

    // 1) x -> fp16
    split_x<<<(unsigned)((RXD / 4 + 255) / 256), 256>>>(x, xh, RXD / 4);

    // 2) weights: transpose to fp16 (Wq|Wk|Wv concat, Wo separate)
    transpose_qkvo<<<dim3(DIM / 32, DIM / 32, 4), dim3(32, 8)>>>(
        Wq, Wk, Wv, Wo, qkvh, woh);

    // 3) fused QKV projection: [8192,1024] @ [1024,3072]
    //    n<2048: Q|K fp16; n>=2048: V^T fp16
    hm1<3,0><<<dim3(3 * DIM / 128, BATCH * SEQ / 128, 1), GT, SMEM_B>>>(
        xh, qkvh, nullptr, qkh, vth,
        2 * DIM, DIM, DIM, DIM, 0, 0, 0);

    // 4) scores = Q @ K^T per batch (compacted lower-triangular tile grid)
    hm1<0,1><<<dim3(136, 1, BATCH), GT, SMEM_B>>>(
        qkh, qkh + DIM, S, nullptr, nullptr,
        SEQ, 2 * DIM, 2 * DIM, DIM, sQK, sQK, sS);

    // 5) softmax -> P fp16
    softmax_causal<<<dim3(SEQ, BATCH), 256>>>(S, ph);

    // 6) AO = P @ V (B = V^T, K-limited, long rows first)
    hm1<1,2><<<dim3(DIM / 128, SEQ / 128, BATCH), GT, SMEM_B>>>(
        ph, vth, nullptr, aoh, nullptr,
        DIM, SEQ, SEQ, SEQ, sS, sV, (size_t)SEQ * DIM);

    // 7) out = AO @ Wo
    hm1<0,0><<<dim3(DIM / 128, BATCH * SEQ / 128, 1), GT, SMEM_B>>>(
        aoh, woh, out, nullptr, nullptr,
        DIM, DIM, DIM, DIM, 0, 0, 0);
}